// round 2
// baseline (speedup 1.0000x reference)
#include <cuda_runtime.h>
#include <math.h>

#define Bn 2
#define Sn 2048
#define En 2048
#define Hn 16
#define NOPEn 64
#define ROPEn 32
#define Vn 64
#define KVRn 256
#define QKDn 96
#define BSn (Bn*Sn)
#define KD 288                       /* KVR + ROPE packed row */
#define SCALEF 0.10206207261596577f  /* 96^-0.5 */
#define NEGB (-1e30f)
#define LN1E4_D128 0.07195578415606394f  /* ln(10000)/128 */
#define LN1E4_D16  0.5756462732485115f   /* ln(10000)/16  */

/* ---------------- scratch (device globals; no allocation) ---------------- */
__device__ __align__(16) float g_q[(size_t)BSn * Hn * QKDn];      // (row, h*96+d)
__device__ __align__(16) float g_kv[(size_t)BSn * KD];            // ln(kv_c) ++ rope(k_pe)
__device__ __align__(16) float g_key[(size_t)BSn * KD];           // kv_t ++ k_pe_t
__device__ __align__(16) float g_qpack[(size_t)Hn * BSn * KD];    // (h,row,288) scaled q_abs++q_pe
__device__ __align__(16) float g_wkT[(size_t)Hn * KVRn * NOPEn];  // (h,c,d)
__device__ __align__(16) float g_C2[Sn * 64];
__device__ __align__(16) float g_P2[Sn * 64];
__device__ __align__(16) float g_x[(size_t)Hn * BSn * KVRn];      // attention out pre-Vproj
__device__ __align__(16) float g_v[(size_t)BSn * Hn * Vn];        // per-head projected

/* ============ batched fp32 GEMM: C = alpha * A[M,K] * B[N,K]^T ============ */
__global__ __launch_bounds__(256) void sgemm_nt(
    const float* __restrict__ A, int lda, long long sA,
    const float* __restrict__ B, int ldb, long long sB,
    float* __restrict__ C, int ldc, long long sC,
    int M, int N, int K, float alpha)
{
  A += (size_t)blockIdx.z * sA;
  B += (size_t)blockIdx.z * sB;
  C += (size_t)blockIdx.z * sC;
  __shared__ float As[8][128];
  __shared__ float Bs[8][128];
  const int tid = threadIdx.x;
  const int bm = blockIdx.y * 128, bn = blockIdx.x * 128;
  const int lr = tid >> 1, lc = (tid & 1) * 4;
  const int ty = tid >> 4, tx = tid & 15;
  float acc[8][8];
#pragma unroll
  for (int i = 0; i < 8; i++)
#pragma unroll
    for (int j = 0; j < 8; j++) acc[i][j] = 0.f;

  for (int kt = 0; kt < K; kt += 8) {
    float4 av = make_float4(0.f, 0.f, 0.f, 0.f);
    float4 bv = make_float4(0.f, 0.f, 0.f, 0.f);
    if (bm + lr < M) av = *(const float4*)(A + (size_t)(bm + lr) * lda + kt + lc);
    if (bn + lr < N) bv = *(const float4*)(B + (size_t)(bn + lr) * ldb + kt + lc);
    __syncthreads();
    As[lc+0][lr]=av.x; As[lc+1][lr]=av.y; As[lc+2][lr]=av.z; As[lc+3][lr]=av.w;
    Bs[lc+0][lr]=bv.x; Bs[lc+1][lr]=bv.y; Bs[lc+2][lr]=bv.z; Bs[lc+3][lr]=bv.w;
    __syncthreads();
#pragma unroll
    for (int kk = 0; kk < 8; kk++) {
      float a[8], bb[8];
      *(float4*)&a[0]  = *(const float4*)&As[kk][ty*8];
      *(float4*)&a[4]  = *(const float4*)&As[kk][ty*8+4];
      *(float4*)&bb[0] = *(const float4*)&Bs[kk][tx*8];
      *(float4*)&bb[4] = *(const float4*)&Bs[kk][tx*8+4];
#pragma unroll
      for (int i = 0; i < 8; i++)
#pragma unroll
        for (int j = 0; j < 8; j++) acc[i][j] += a[i]*bb[j];
    }
  }
#pragma unroll
  for (int i = 0; i < 8; i++) {
    int row = bm + ty*8 + i;
    if (row >= M) continue;
    int col = bn + tx*8;
    if (col < N) {
      float4 v0 = make_float4(alpha*acc[i][0], alpha*acc[i][1], alpha*acc[i][2], alpha*acc[i][3]);
      float4 v1 = make_float4(alpha*acc[i][4], alpha*acc[i][5], alpha*acc[i][6], alpha*acc[i][7]);
      *(float4*)(C + (size_t)row*ldc + col)     = v0;
      *(float4*)(C + (size_t)row*ldc + col + 4) = v1;
    }
  }
}

/* ============ C2/P2 projections of the positional encodings ============ */
__global__ void gateproj_kernel(const float* __restrict__ cw, const float* __restrict__ cb,
                                const float* __restrict__ pw, const float* __restrict__ pb) {
  int s = blockIdx.x;
  int tid = threadIdx.x;   // 64 threads
  __shared__ float prow[256], crow[256];
  for (int k = tid; k < 256; k += 64) {
    int i = k >> 1;
    float dv = expf(-(float)i * LN1E4_D128);
    float aP = (float)s * dv;
    float aC = (float)(s >> 1) * dv;
    prow[k] = (k & 1) ? cosf(aP) : sinf(aP);
    crow[k] = (k & 1) ? cosf(aC) : sinf(aC);
  }
  __syncthreads();
  float ap = pb[tid], ac = cb[tid];
  const float* pr = pw + tid * 256;
  const float* cr = cw + tid * 256;
  for (int k = 0; k < 256; k++) { ap += prow[k] * pr[k]; ac += crow[k] * cr[k]; }
  g_P2[s*64 + tid] = ap;
  g_C2[s*64 + tid] = ac;
}

/* ============ layernorm(kv_c) + rope(k_pe) in place on g_kv ============ */
__global__ void ln_rope_kernel(const float* __restrict__ gam, const float* __restrict__ bet) {
  int row = blockIdx.x;
  float* kv = g_kv + (size_t)row * KD;
  int tid = threadIdx.x;   // 256
  float x = kv[tid];
  float s1 = x, s2 = x * x;
#pragma unroll
  for (int o = 16; o; o >>= 1) {
    s1 += __shfl_xor_sync(0xffffffffu, s1, o);
    s2 += __shfl_xor_sync(0xffffffffu, s2, o);
  }
  __shared__ float r1[8], r2[8], mv[2];
  int lane = tid & 31, wid = tid >> 5;
  if (lane == 0) { r1[wid] = s1; r2[wid] = s2; }
  __syncthreads();
  if (tid == 0) {
    float a = 0.f, c = 0.f;
#pragma unroll
    for (int i = 0; i < 8; i++) { a += r1[i]; c += r2[i]; }
    float mean = a * (1.f / 256.f);
    mv[0] = mean;
    mv[1] = rsqrtf(c * (1.f / 256.f) - mean * mean + 1e-5f);
  }
  __syncthreads();
  kv[tid] = (x - mv[0]) * mv[1] * gam[tid] + bet[tid];
  if (tid < 16) {
    int s = row & (Sn - 1);
    float freq = expf(-(float)tid * LN1E4_D16);
    float ang = (float)s * freq;
    float cs = cosf(ang), sn = sinf(ang);
    float x0 = kv[256 + 2*tid], x1 = kv[256 + 2*tid + 1];
    kv[256 + 2*tid]     = x0*cs - x1*sn;
    kv[256 + 2*tid + 1] = x0*sn + x1*cs;
  }
}

/* ============ sparse Wg gating: g_key = kv_t ++ k_pe_t ============ */
__global__ void gate_kernel() {
  int row = blockIdx.x;
  int s = row & (Sn - 1);
  int tid = threadIdx.x;   // 128
  __shared__ float d1[64], d2[64], w2[2];
  if (tid < 64) {
    float c2 = g_C2[s*64 + tid];
    d1[tid] = c2 * g_P2[s*64 + tid];
    d2[tid] = (s & 1) ? c2 * g_P2[(s-1)*64 + tid] : 0.f;
  }
  __syncthreads();
  if (tid == 0) {
    float a = 0.f, b = 0.f;
    for (int i = 0; i < 64; i++) { a += d1[i]; b += d2[i]; }
    w2[0] = 1.f / (1.f + expf(-a));
    w2[1] = 1.f / (1.f + expf(-b));
  }
  __syncthreads();
  float wtt = w2[0], wpre = w2[1];
  const float* kvr = g_kv + (size_t)row * KD;
  float* dst = g_key + (size_t)row * KD;
  if (s & 1) {
    const float* kvp = kvr - KD;
    for (int c = tid; c < KD; c += 128) dst[c] = wtt * kvr[c] + wpre * kvp[c];
  } else {
    for (int c = tid; c < KD; c += 128) dst[c] = wtt * kvr[c];
  }
}

/* ============ transpose wkv_b first-64 rows per head: g_wkT[h][c][d] ============ */
__global__ void wkT_kernel(const float* __restrict__ wkvb) {
  int idx = blockIdx.x * 256 + threadIdx.x;   // < 16*256*64
  int d = idx & 63;
  int c = (idx >> 6) & 255;
  int h = idx >> 14;
  g_wkT[((size_t)h * 256 + c) * 64 + d] = wkvb[((size_t)h * 128 + d) * 256 + c];
}

/* ============ rope + scale q_pe into g_qpack[...,256:288] ============ */
__global__ void qpack_kernel() {
  int row = blockIdx.x;
  int tid = threadIdx.x;     // 256 = 16 heads * 16 pairs
  int h = tid >> 4, i = tid & 15;
  int s = row & (Sn - 1);
  const float* p = g_q + (size_t)row * (Hn*QKDn) + h*QKDn + NOPEn + 2*i;
  float freq = expf(-(float)i * LN1E4_D16);
  float ang = (float)s * freq;
  float cs = cosf(ang), sn = sinf(ang);
  float x0 = p[0], x1 = p[1];
  float* q = g_qpack + ((size_t)h * BSn + row) * KD + 256 + 2*i;
  q[0] = (x0*cs - x1*sn) * SCALEF;
  q[1] = (x0*sn + x1*cs) * SCALEF;
}

/* ============ flash attention over compacted odd keys + diagonal ============ */
#define ATT_SMEM_FLOATS (288*65 + 288*33 + 64*33 + 192)

__global__ __launch_bounds__(256, 1) void attn_kernel() {
  extern __shared__ float sm[];
  float* QT   = sm;               // [288][65]
  float* KT   = QT + 288*65;      // [288][33]
  float* P    = KT + 288*33;      // [64][33]  (col 32 = diag prob)
  float* mrow = P + 64*33;
  float* lrow = mrow + 64;
  float* scl  = lrow + 64;

  const int tid = threadIdx.x;
  const int ty = tid >> 4, tx = tid & 15;
  const int lane = tid & 31, w = tid >> 5;

  int idx = blockIdx.x;
  int qt = 31 - (idx & 31);     // reversed for load balance
  int bh = idx >> 5;
  int h = bh & 15, b = bh >> 4;
  int s0 = qt * 64;

  const float* qbase = g_qpack + ((size_t)h * BSn + (size_t)b * Sn + s0) * KD;
  for (int i2 = tid; i2 < 64*KD; i2 += 256) {
    int q = i2 / KD, d = i2 - q*KD;
    QT[d*65 + q] = qbase[(size_t)q * KD + d];
  }
  if (tid < 64) { mrow[tid] = NEGB; lrow[tid] = 0.f; }
  float acc[4][16];
#pragma unroll
  for (int i = 0; i < 4; i++)
#pragma unroll
    for (int c = 0; c < 16; c++) acc[i][c] = 0.f;
  __syncthreads();

  const float* keyb = g_key + (size_t)b * Sn * KD;

  for (int it = 0; it <= qt; it++) {
    /* load 32 odd keys t = 2*(32*it+j)+1, transposed */
    for (int i2 = tid; i2 < 32*KD; i2 += 256) {
      int j = i2 / KD, d = i2 - j*KD;
      int t = 2*(32*it + j) + 1;
      KT[d*33 + j] = keyb[(size_t)t * KD + d];
    }
    __syncthreads();

    /* scores 64x32 = QT^T * KT */
    float c8[4][2];
#pragma unroll
    for (int i = 0; i < 4; i++) { c8[i][0] = 0.f; c8[i][1] = 0.f; }
#pragma unroll 4
    for (int kd = 0; kd < KD; kd++) {
      float a0 = QT[kd*65 + ty*4+0];
      float a1 = QT[kd*65 + ty*4+1];
      float a2 = QT[kd*65 + ty*4+2];
      float a3 = QT[kd*65 + ty*4+3];
      float b0 = KT[kd*33 + tx*2+0];
      float b1 = KT[kd*33 + tx*2+1];
      c8[0][0] += a0*b0; c8[0][1] += a0*b1;
      c8[1][0] += a1*b0; c8[1][1] += a1*b1;
      c8[2][0] += a2*b0; c8[2][1] += a2*b1;
      c8[3][0] += a3*b0; c8[3][1] += a3*b1;
    }
#pragma unroll
    for (int i = 0; i < 4; i++) {
      P[(ty*4+i)*33 + tx*2+0] = c8[i][0];
      P[(ty*4+i)*33 + tx*2+1] = c8[i][1];
    }
    __syncthreads();

    /* online softmax; warp w owns rows 8w..8w+7 */
    bool lastt = (it == qt);
    for (int rr = 0; rr < 8; rr++) {
      int r = w*8 + rr;
      float sc = P[r*33 + lane];
      if (lastt && (2*lane + 1 > r)) sc = NEGB;
      float mx = sc;
#pragma unroll
      for (int o = 16; o; o >>= 1) mx = fmaxf(mx, __shfl_xor_sync(0xffffffffu, mx, o));
      float mold = mrow[r];
      float mnew = fmaxf(mold, mx);
      float p = expf(sc - mnew);
      float su = p;
#pragma unroll
      for (int o = 16; o; o >>= 1) su += __shfl_xor_sync(0xffffffffu, su, o);
      P[r*33 + lane] = p;
      if (lane == 0) {
        float s = expf(mold - mnew);
        scl[r] = s;
        lrow[r] = lrow[r]*s + su;
        mrow[r] = mnew;
      }
    }
    __syncthreads();

    /* rescale + PV: acc[q][c] += p[q][j] * kv_t[j][c] (first 256 dims) */
    float s4[4];
#pragma unroll
    for (int i = 0; i < 4; i++) s4[i] = scl[ty*4+i];
#pragma unroll
    for (int i = 0; i < 4; i++)
#pragma unroll
      for (int c = 0; c < 16; c++) acc[i][c] *= s4[i];
    for (int j = 0; j < 32; j++) {
      float p4[4];
#pragma unroll
      for (int i = 0; i < 4; i++) p4[i] = P[(ty*4+i)*33 + j];
#pragma unroll
      for (int c = 0; c < 16; c++) {
        float kv = KT[(c*16 + tx)*33 + j];
#pragma unroll
        for (int i = 0; i < 4; i++) acc[i][c] += p4[i]*kv;
      }
    }
    __syncthreads();
  }

  /* diagonal keys: s = s0 + 2*j (only even queries need them) */
  for (int i2 = tid; i2 < 32*KD; i2 += 256) {
    int j = i2 / KD, d = i2 - j*KD;
    KT[d*33 + j] = keyb[(size_t)(s0 + 2*j) * KD + d];
  }
  __syncthreads();
  for (int rr = 0; rr < 8; rr++) {
    int r = w*8 + rr;
    float dot = 0.f;
    if (!(r & 1)) {
      int jj = r >> 1;
      for (int d = lane; d < KD; d += 32) dot += QT[d*65 + r] * KT[d*33 + jj];
#pragma unroll
      for (int o = 16; o; o >>= 1) dot += __shfl_xor_sync(0xffffffffu, dot, o);
    }
    if (lane == 0) {
      if (!(r & 1)) {
        float mold = mrow[r], mnew = fmaxf(mold, dot);
        float s = expf(mold - mnew);
        float pd = expf(dot - mnew);
        scl[r] = s;
        P[r*33 + 32] = pd;
        lrow[r] = lrow[r]*s + pd;
        mrow[r] = mnew;
      } else {
        scl[r] = 1.f;
        P[r*33 + 32] = 0.f;
      }
    }
  }
  __syncthreads();

  /* final rescale + diag add + /l + writeout */
  float* xb = g_x + ((size_t)h * BSn + (size_t)b * Sn + s0) * 256;
#pragma unroll
  for (int i = 0; i < 4; i++) {
    int q = ty*4 + i;
    float s = scl[q];
    float pd = P[q*33 + 32];
    int jj = q >> 1;
    float invl = 1.f / lrow[q];
#pragma unroll
    for (int c = 0; c < 16; c++) {
      float v = acc[i][c]*s + pd * KT[(c*16 + tx)*33 + jj];
      xb[(size_t)q*256 + c*16 + tx] = v * invl;
    }
  }
}

extern "C" void kernel_launch(void* const* d_in, const int* in_sizes, int n_in,
                              void* d_out, int out_size) {
  const float* hidden = (const float*)d_in[0];
  const float* wq     = (const float*)d_in[1];
  const float* wkv_a  = (const float*)d_in[2];
  const float* kvg    = (const float*)d_in[3];
  const float* kvb    = (const float*)d_in[4];
  const float* wkvb   = (const float*)d_in[5];
  const float* wo     = (const float*)d_in[6];
  const float* fcw    = (const float*)d_in[7];
  const float* fcb    = (const float*)d_in[8];
  const float* fpw    = (const float*)d_in[9];
  const float* fpb    = (const float*)d_in[10];
  float* out = (float*)d_out;

  float *pq, *pkv, *pqpack, *pwkT, *px, *pv;
  cudaGetSymbolAddress((void**)&pq, g_q);
  cudaGetSymbolAddress((void**)&pkv, g_kv);
  cudaGetSymbolAddress((void**)&pqpack, g_qpack);
  cudaGetSymbolAddress((void**)&pwkT, g_wkT);
  cudaGetSymbolAddress((void**)&px, g_x);
  cudaGetSymbolAddress((void**)&pv, g_v);

  /* q = hidden @ wq^T  (4096 x 1536, K=2048) */
  sgemm_nt<<<dim3(12, 32, 1), 256>>>(hidden, 2048, 0, wq, 2048, 0,
                                     pq, 1536, 0, 4096, 1536, 2048, 1.f);
  /* kv = hidden @ wkv_a^T  (4096 x 288, K=2048) */
  sgemm_nt<<<dim3(3, 32, 1), 256>>>(hidden, 2048, 0, wkv_a, 2048, 0,
                                    pkv, KD, 0, 4096, KD, 2048, 1.f);
  gateproj_kernel<<<Sn, 64>>>(fcw, fcb, fpw, fpb);
  ln_rope_kernel<<<BSn, 256>>>(kvg, kvb);
  gate_kernel<<<BSn, 128>>>();
  wkT_kernel<<<(Hn*KVRn*NOPEn)/256, 256>>>(wkvb);
  qpack_kernel<<<BSn, 256>>>();
  /* q_abs per head: (4096 x 256, K=64), scaled, into g_qpack cols 0..255 */
  sgemm_nt<<<dim3(2, 32, 16), 256>>>(pq, Hn*QKDn, QKDn,
                                     pwkT, NOPEn, (long long)KVRn*NOPEn,
                                     pqpack, KD, (long long)BSn*KD,
                                     4096, KVRn, NOPEn, SCALEF);
  cudaFuncSetAttribute(attn_kernel, cudaFuncAttributeMaxDynamicSharedMemorySize,
                       ATT_SMEM_FLOATS * 4);
  attn_kernel<<<Bn*Hn*32, 256, ATT_SMEM_FLOATS * 4>>>();
  /* v-proj per head: (4096 x 64, K=256) into g_v columns h*64.. */
  sgemm_nt<<<dim3(1, 32, 16), 256>>>(px, KVRn, (long long)BSn*KVRn,
                                     wkvb + 64*256, KVRn, (long long)128*256,
                                     pv, Hn*Vn, Vn,
                                     4096, Vn, KVRn, 1.f);
  /* final = v @ wo^T (4096 x 2048, K=1024) */
  sgemm_nt<<<dim3(16, 32, 1), 256>>>(pv, Hn*Vn, 0, wo, Hn*Vn, 0,
                                     out, En, 0, 4096, En, Hn*Vn, 1.f);
}

// round 4
// speedup vs baseline: 1.2420x; 1.2420x over previous
#include <cuda_runtime.h>
#include <cuda_bf16.h>
#include <math.h>
#include <stdint.h>

#define Bn 2
#define Sn 2048
#define En 2048
#define Hn 16
#define NOPEn 64
#define ROPEn 32
#define Vn 64
#define KVRn 256
#define QKDn 96
#define BSn (Bn*Sn)
#define KD 288                       /* KVR + ROPE packed row */
#define SCALEF 0.10206207261596577f  /* 96^-0.5 */
#define NEGB (-1e30f)
#define LN1E4_D128 0.07195578415606394f  /* ln(10000)/128 */
#define LN1E4_D16  0.5756462732485115f   /* ln(10000)/16  */

/* ---------------- scratch (device globals; no allocation) ---------------- */
__device__ __align__(16) float g_q[(size_t)BSn * Hn * QKDn];      // (row, h*96+d)
__device__ __align__(16) float g_kv[(size_t)BSn * KD];            // ln(kv_c) ++ rope(k_pe)
__device__ __align__(16) float g_key[(size_t)BSn * KD];           // kv_t ++ k_pe_t
__device__ __align__(16) float g_qpack[(size_t)Hn * BSn * KD];    // (h,row,288)
__device__ __align__(16) float g_wkT[(size_t)Hn * KVRn * NOPEn];  // (h,c,d)
__device__ __align__(16) float g_C2[Sn * 64];
__device__ __align__(16) float g_P2[Sn * 64];
__device__ __align__(16) float g_x[(size_t)Hn * BSn * KVRn];      // attention out pre-Vproj
__device__ __align__(16) float g_v[(size_t)BSn * Hn * Vn];        // per-head projected

/* ==================== mma.sync helpers ==================== */
__device__ __forceinline__ void mma16816(float* c, const uint32_t* a, const uint32_t* b) {
  asm volatile(
    "mma.sync.aligned.m16n8k16.row.col.f32.bf16.bf16.f32 "
    "{%0,%1,%2,%3}, {%4,%5,%6,%7}, {%8,%9}, {%0,%1,%2,%3};"
    : "+f"(c[0]), "+f"(c[1]), "+f"(c[2]), "+f"(c[3])
    : "r"(a[0]), "r"(a[1]), "r"(a[2]), "r"(a[3]), "r"(b[0]), "r"(b[1]));
}

__device__ __forceinline__ uint32_t pack_hi(float x, float y) {
  __nv_bfloat16 hx = __float2bfloat16_rn(x);
  __nv_bfloat16 hy = __float2bfloat16_rn(y);
  return ((uint32_t)__bfloat16_as_ushort(hy) << 16) | __bfloat16_as_ushort(hx);
}
__device__ __forceinline__ uint32_t pack_lo(float x, float y) {
  __nv_bfloat16 hx = __float2bfloat16_rn(x);
  __nv_bfloat16 hy = __float2bfloat16_rn(y);
  __nv_bfloat16 lx = __float2bfloat16_rn(x - __bfloat162float(hx));
  __nv_bfloat16 ly = __float2bfloat16_rn(y - __bfloat162float(hy));
  return ((uint32_t)__bfloat16_as_ushort(ly) << 16) | __bfloat16_as_ushort(lx);
}

/* =============== tensor-core fp32-split GEMM: C = alpha*A[M,K]*B[N,K]^T ===============
   128x128 CTA tile, 8 warps (2x4), 64x32 warp tile, K-chunk 32, bf16 hi/lo 3-MMA.
   smem pitch = 20 words (40 bf16) per row -> conflict-free fragment loads. */
#define PITCH 20

__global__ __launch_bounds__(256, 1) void tgemm(
    const float* __restrict__ A, int lda,
    const float* __restrict__ B, int ldb,
    float* __restrict__ C, int ldc,
    int M, int N, int K, float alpha)
{
  __shared__ uint32_t smAh[128 * PITCH];
  __shared__ uint32_t smAl[128 * PITCH];
  __shared__ uint32_t smBh[128 * PITCH];
  __shared__ uint32_t smBl[128 * PITCH];

  const int tid = threadIdx.x;
  const int wid = tid >> 5, lane = tid & 31;
  const int g = lane >> 2, q = lane & 3;
  const int wm = (wid & 1) * 64;        // warp M offset
  const int wn = (wid >> 1) * 32;       // warp N offset
  const int bm = blockIdx.y * 128, bn = blockIdx.x * 128;

  const int lrow = tid >> 1, lc = (tid & 1) * 16;
  const bool aok = (bm + lrow < M);
  const bool bok = (bn + lrow < N);
  const float* Arow = A + (size_t)(bm + lrow) * lda + lc;
  const float* Brow = B + (size_t)(bn + lrow) * ldb + lc;

  float acc[4][4][4];
#pragma unroll
  for (int i = 0; i < 4; i++)
#pragma unroll
    for (int j = 0; j < 4; j++)
#pragma unroll
      for (int t = 0; t < 4; t++) acc[i][j][t] = 0.f;

  float4 aR[4], bR[4];
  const float4 z4 = make_float4(0.f, 0.f, 0.f, 0.f);
#pragma unroll
  for (int i = 0; i < 4; i++) {
    aR[i] = aok ? *(const float4*)(Arow + 4 * i) : z4;
    bR[i] = bok ? *(const float4*)(Brow + 4 * i) : z4;
  }

  const int nk = K >> 5;
  for (int k = 0; k < nk; k++) {
    /* stage current regs -> smem (hi/lo split) */
    {
      int wo = lrow * PITCH + (lc >> 1);
#pragma unroll
      for (int i = 0; i < 4; i++) {
        float4 a = aR[i], b = bR[i];
        uint2 ah = make_uint2(pack_hi(a.x, a.y), pack_hi(a.z, a.w));
        uint2 al = make_uint2(pack_lo(a.x, a.y), pack_lo(a.z, a.w));
        uint2 bh = make_uint2(pack_hi(b.x, b.y), pack_hi(b.z, b.w));
        uint2 bl = make_uint2(pack_lo(b.x, b.y), pack_lo(b.z, b.w));
        *(uint2*)&smAh[wo + 2 * i] = ah;
        *(uint2*)&smAl[wo + 2 * i] = al;
        *(uint2*)&smBh[wo + 2 * i] = bh;
        *(uint2*)&smBl[wo + 2 * i] = bl;
      }
    }
    __syncthreads();
    /* prefetch next chunk */
    if (k + 1 < nk) {
      int off = (k + 1) << 5;
#pragma unroll
      for (int i = 0; i < 4; i++) {
        aR[i] = aok ? *(const float4*)(Arow + off + 4 * i) : z4;
        bR[i] = bok ? *(const float4*)(Brow + off + 4 * i) : z4;
      }
    }
    /* compute: 2 k16 steps */
#pragma unroll
    for (int ks = 0; ks < 2; ks++) {
      uint32_t bh[4][2], bl[4][2];
#pragma unroll
      for (int nt = 0; nt < 4; nt++) {
        int r = (wn + nt * 8 + g) * PITCH + ks * 8 + q;
        bh[nt][0] = smBh[r]; bh[nt][1] = smBh[r + 4];
        bl[nt][0] = smBl[r]; bl[nt][1] = smBl[r + 4];
      }
#pragma unroll
      for (int mt = 0; mt < 4; mt++) {
        int r = (wm + mt * 16 + g) * PITCH + ks * 8 + q;
        uint32_t ah[4], al[4];
        ah[0] = smAh[r];            ah[1] = smAh[r + 8 * PITCH];
        ah[2] = smAh[r + 4];        ah[3] = smAh[r + 8 * PITCH + 4];
        al[0] = smAl[r];            al[1] = smAl[r + 8 * PITCH];
        al[2] = smAl[r + 4];        al[3] = smAl[r + 8 * PITCH + 4];
#pragma unroll
        for (int nt = 0; nt < 4; nt++) {
          mma16816(acc[mt][nt], ah, bh[nt]);
          mma16816(acc[mt][nt], ah, bl[nt]);
          mma16816(acc[mt][nt], al, bh[nt]);
        }
      }
    }
    __syncthreads();
  }

  /* epilogue */
#pragma unroll
  for (int mt = 0; mt < 4; mt++) {
    int row = bm + wm + mt * 16 + g;
#pragma unroll
    for (int nt = 0; nt < 4; nt++) {
      int col = bn + wn + nt * 8 + q * 2;
      if (col < N) {
        if (row < M)
          *(float2*)(C + (size_t)row * ldc + col) =
            make_float2(alpha * acc[mt][nt][0], alpha * acc[mt][nt][1]);
        if (row + 8 < M)
          *(float2*)(C + (size_t)(row + 8) * ldc + col) =
            make_float2(alpha * acc[mt][nt][2], alpha * acc[mt][nt][3]);
      }
    }
  }
}

/* ============ batched fp32 GEMM (small cases): C = alpha*A[M,K]*B[N,K]^T ============ */
__global__ __launch_bounds__(256) void sgemm_nt(
    const float* __restrict__ A, int lda, long long sA,
    const float* __restrict__ B, int ldb, long long sB,
    float* __restrict__ C, int ldc, long long sC,
    int M, int N, int K, float alpha)
{
  A += (size_t)blockIdx.z * sA;
  B += (size_t)blockIdx.z * sB;
  C += (size_t)blockIdx.z * sC;
  __shared__ float As[8][128];
  __shared__ float Bs[8][128];
  const int tid = threadIdx.x;
  const int bm = blockIdx.y * 128, bn = blockIdx.x * 128;
  const int lr = tid >> 1, lc = (tid & 1) * 4;
  const int ty = tid >> 4, tx = tid & 15;
  float acc[8][8];
#pragma unroll
  for (int i = 0; i < 8; i++)
#pragma unroll
    for (int j = 0; j < 8; j++) acc[i][j] = 0.f;

  for (int kt = 0; kt < K; kt += 8) {
    float4 av = make_float4(0.f, 0.f, 0.f, 0.f);
    float4 bv = make_float4(0.f, 0.f, 0.f, 0.f);
    if (bm + lr < M) av = *(const float4*)(A + (size_t)(bm + lr) * lda + kt + lc);
    if (bn + lr < N) bv = *(const float4*)(B + (size_t)(bn + lr) * ldb + kt + lc);
    __syncthreads();
    As[lc+0][lr]=av.x; As[lc+1][lr]=av.y; As[lc+2][lr]=av.z; As[lc+3][lr]=av.w;
    Bs[lc+0][lr]=bv.x; Bs[lc+1][lr]=bv.y; Bs[lc+2][lr]=bv.z; Bs[lc+3][lr]=bv.w;
    __syncthreads();
#pragma unroll
    for (int kk = 0; kk < 8; kk++) {
      float a[8], bb[8];
      *(float4*)&a[0]  = *(const float4*)&As[kk][ty*8];
      *(float4*)&a[4]  = *(const float4*)&As[kk][ty*8+4];
      *(float4*)&bb[0] = *(const float4*)&Bs[kk][tx*8];
      *(float4*)&bb[4] = *(const float4*)&Bs[kk][tx*8+4];
#pragma unroll
      for (int i = 0; i < 8; i++)
#pragma unroll
        for (int j = 0; j < 8; j++) acc[i][j] += a[i]*bb[j];
    }
  }
#pragma unroll
  for (int i = 0; i < 8; i++) {
    int row = bm + ty*8 + i;
    if (row >= M) continue;
    int col = bn + tx*8;
    if (col < N) {
      float4 v0 = make_float4(alpha*acc[i][0], alpha*acc[i][1], alpha*acc[i][2], alpha*acc[i][3]);
      float4 v1 = make_float4(alpha*acc[i][4], alpha*acc[i][5], alpha*acc[i][6], alpha*acc[i][7]);
      *(float4*)(C + (size_t)row*ldc + col)     = v0;
      *(float4*)(C + (size_t)row*ldc + col + 4) = v1;
    }
  }
}

/* ============ C2/P2 projections of the positional encodings ============ */
__global__ void gateproj_kernel(const float* __restrict__ cw, const float* __restrict__ cb,
                                const float* __restrict__ pw, const float* __restrict__ pb) {
  int s = blockIdx.x;
  int tid = threadIdx.x;   // 64 threads
  __shared__ float prow[256], crow[256];
  for (int k = tid; k < 256; k += 64) {
    int i = k >> 1;
    float dv = expf(-(float)i * LN1E4_D128);
    float aP = (float)s * dv;
    float aC = (float)(s >> 1) * dv;
    prow[k] = (k & 1) ? cosf(aP) : sinf(aP);
    crow[k] = (k & 1) ? cosf(aC) : sinf(aC);
  }
  __syncthreads();
  float ap = pb[tid], ac = cb[tid];
  const float* pr = pw + tid * 256;
  const float* cr = cw + tid * 256;
  for (int k = 0; k < 256; k++) { ap += prow[k] * pr[k]; ac += crow[k] * cr[k]; }
  g_P2[s*64 + tid] = ap;
  g_C2[s*64 + tid] = ac;
}

/* ============ layernorm(kv_c) + rope(k_pe) in place on g_kv ============ */
__global__ void ln_rope_kernel(const float* __restrict__ gam, const float* __restrict__ bet) {
  int row = blockIdx.x;
  float* kv = g_kv + (size_t)row * KD;
  int tid = threadIdx.x;   // 256
  float x = kv[tid];
  float s1 = x, s2 = x * x;
#pragma unroll
  for (int o = 16; o; o >>= 1) {
    s1 += __shfl_xor_sync(0xffffffffu, s1, o);
    s2 += __shfl_xor_sync(0xffffffffu, s2, o);
  }
  __shared__ float r1[8], r2[8], mv[2];
  int lane = tid & 31, wid = tid >> 5;
  if (lane == 0) { r1[wid] = s1; r2[wid] = s2; }
  __syncthreads();
  if (tid == 0) {
    float a = 0.f, c = 0.f;
#pragma unroll
    for (int i = 0; i < 8; i++) { a += r1[i]; c += r2[i]; }
    float mean = a * (1.f / 256.f);
    mv[0] = mean;
    mv[1] = rsqrtf(c * (1.f / 256.f) - mean * mean + 1e-5f);
  }
  __syncthreads();
  kv[tid] = (x - mv[0]) * mv[1] * gam[tid] + bet[tid];
  if (tid < 16) {
    int s = row & (Sn - 1);
    float freq = expf(-(float)tid * LN1E4_D16);
    float ang = (float)s * freq;
    float cs = cosf(ang), sn = sinf(ang);
    float x0 = kv[256 + 2*tid], x1 = kv[256 + 2*tid + 1];
    kv[256 + 2*tid]     = x0*cs - x1*sn;
    kv[256 + 2*tid + 1] = x0*sn + x1*cs;
  }
}

/* ============ sparse Wg gating: g_key = kv_t ++ k_pe_t ============ */
__global__ void gate_kernel() {
  int row = blockIdx.x;
  int s = row & (Sn - 1);
  int tid = threadIdx.x;   // 128
  __shared__ float d1[64], d2[64], w2[2];
  if (tid < 64) {
    float c2 = g_C2[s*64 + tid];
    d1[tid] = c2 * g_P2[s*64 + tid];
    d2[tid] = (s & 1) ? c2 * g_P2[(s-1)*64 + tid] : 0.f;
  }
  __syncthreads();
  if (tid == 0) {
    float a = 0.f, b = 0.f;
    for (int i = 0; i < 64; i++) { a += d1[i]; b += d2[i]; }
    w2[0] = 1.f / (1.f + expf(-a));
    w2[1] = 1.f / (1.f + expf(-b));
  }
  __syncthreads();
  float wtt = w2[0], wpre = w2[1];
  const float* kvr = g_kv + (size_t)row * KD;
  float* dst = g_key + (size_t)row * KD;
  if (s & 1) {
    const float* kvp = kvr - KD;
    for (int c = tid; c < KD; c += 128) dst[c] = wtt * kvr[c] + wpre * kvp[c];
  } else {
    for (int c = tid; c < KD; c += 128) dst[c] = wtt * kvr[c];
  }
}

/* ============ transpose wkv_b first-64 rows per head: g_wkT[h][c][d] ============ */
__global__ void wkT_kernel(const float* __restrict__ wkvb) {
  int idx = blockIdx.x * 256 + threadIdx.x;   // < 16*256*64
  int d = idx & 63;
  int c = (idx >> 6) & 255;
  int h = idx >> 14;
  g_wkT[((size_t)h * 256 + c) * 64 + d] = wkvb[((size_t)h * 128 + d) * 256 + c];
}

/* ============ rope + scale q_pe into g_qpack[...,256:288] ============ */
__global__ void qpack_kernel() {
  int row = blockIdx.x;
  int tid = threadIdx.x;     // 256 = 16 heads * 16 pairs
  int h = tid >> 4, i = tid & 15;
  int s = row & (Sn - 1);
  const float* p = g_q + (size_t)row * (Hn*QKDn) + h*QKDn + NOPEn + 2*i;
  float freq = expf(-(float)i * LN1E4_D16);
  float ang = (float)s * freq;
  float cs = cosf(ang), sn = sinf(ang);
  float x0 = p[0], x1 = p[1];
  float* q = g_qpack + ((size_t)h * BSn + row) * KD + 256 + 2*i;
  q[0] = (x0*cs - x1*sn) * SCALEF;
  q[1] = (x0*sn + x1*cs) * SCALEF;
}

/* ============ flash attention over compacted odd keys + diagonal ============ */
#define ATT_SMEM_FLOATS (288*65 + 288*33 + 64*33 + 192)

__global__ __launch_bounds__(256, 1) void attn_kernel() {
  extern __shared__ float sm[];
  float* QT   = sm;               // [288][65]
  float* KT   = QT + 288*65;      // [288][33]
  float* P    = KT + 288*33;      // [64][33]  (col 32 = diag prob)
  float* mrow = P + 64*33;
  float* lrow = mrow + 64;
  float* scl  = lrow + 64;

  const int tid = threadIdx.x;
  const int ty = tid >> 4, tx = tid & 15;
  const int lane = tid & 31, w = tid >> 5;

  int idx = blockIdx.x;
  int qt = 31 - (idx & 31);     // reversed for load balance
  int bh = idx >> 5;
  int h = bh & 15, b = bh >> 4;
  int s0 = qt * 64;

  const float* qbase = g_qpack + ((size_t)h * BSn + (size_t)b * Sn + s0) * KD;
  for (int i2 = tid; i2 < 64*KD; i2 += 256) {
    int q = i2 / KD, d = i2 - q*KD;
    QT[d*65 + q] = qbase[(size_t)q * KD + d];
  }
  if (tid < 64) { mrow[tid] = NEGB; lrow[tid] = 0.f; }
  float acc[4][16];
#pragma unroll
  for (int i = 0; i < 4; i++)
#pragma unroll
    for (int c = 0; c < 16; c++) acc[i][c] = 0.f;
  __syncthreads();

  const float* keyb = g_key + (size_t)b * Sn * KD;

  for (int it = 0; it <= qt; it++) {
    /* load 32 odd keys t = 2*(32*it+j)+1, transposed */
    for (int i2 = tid; i2 < 32*KD; i2 += 256) {
      int j = i2 / KD, d = i2 - j*KD;
      int t = 2*(32*it + j) + 1;
      KT[d*33 + j] = keyb[(size_t)t * KD + d];
    }
    __syncthreads();

    /* scores 64x32 = QT^T * KT */
    float c8[4][2];
#pragma unroll
    for (int i = 0; i < 4; i++) { c8[i][0] = 0.f; c8[i][1] = 0.f; }
#pragma unroll 4
    for (int kd = 0; kd < KD; kd++) {
      float a0 = QT[kd*65 + ty*4+0];
      float a1 = QT[kd*65 + ty*4+1];
      float a2 = QT[kd*65 + ty*4+2];
      float a3 = QT[kd*65 + ty*4+3];
      float b0 = KT[kd*33 + tx*2+0];
      float b1 = KT[kd*33 + tx*2+1];
      c8[0][0] += a0*b0; c8[0][1] += a0*b1;
      c8[1][0] += a1*b0; c8[1][1] += a1*b1;
      c8[2][0] += a2*b0; c8[2][1] += a2*b1;
      c8[3][0] += a3*b0; c8[3][1] += a3*b1;
    }
#pragma unroll
    for (int i = 0; i < 4; i++) {
      P[(ty*4+i)*33 + tx*2+0] = c8[i][0];
      P[(ty*4+i)*33 + tx*2+1] = c8[i][1];
    }
    __syncthreads();

    /* online softmax; warp w owns rows 8w..8w+7 */
    bool lastt = (it == qt);
    for (int rr = 0; rr < 8; rr++) {
      int r = w*8 + rr;
      float sc = P[r*33 + lane];
      if (lastt && (2*lane + 1 > r)) sc = NEGB;
      float mx = sc;
#pragma unroll
      for (int o = 16; o; o >>= 1) mx = fmaxf(mx, __shfl_xor_sync(0xffffffffu, mx, o));
      float mold = mrow[r];
      float mnew = fmaxf(mold, mx);
      float p = expf(sc - mnew);
      float su = p;
#pragma unroll
      for (int o = 16; o; o >>= 1) su += __shfl_xor_sync(0xffffffffu, su, o);
      P[r*33 + lane] = p;
      if (lane == 0) {
        float s = expf(mold - mnew);
        scl[r] = s;
        lrow[r] = lrow[r]*s + su;
        mrow[r] = mnew;
      }
    }
    __syncthreads();

    /* rescale + PV: acc[q][c] += p[q][j] * kv_t[j][c] (first 256 dims) */
    float s4[4];
#pragma unroll
    for (int i = 0; i < 4; i++) s4[i] = scl[ty*4+i];
#pragma unroll
    for (int i = 0; i < 4; i++)
#pragma unroll
      for (int c = 0; c < 16; c++) acc[i][c] *= s4[i];
    for (int j = 0; j < 32; j++) {
      float p4[4];
#pragma unroll
      for (int i = 0; i < 4; i++) p4[i] = P[(ty*4+i)*33 + j];
#pragma unroll
      for (int c = 0; c < 16; c++) {
        float kv = KT[(c*16 + tx)*33 + j];
#pragma unroll
        for (int i = 0; i < 4; i++) acc[i][c] += p4[i]*kv;
      }
    }
    __syncthreads();
  }

  /* diagonal keys: s = s0 + 2*j (only even queries need them) */
  for (int i2 = tid; i2 < 32*KD; i2 += 256) {
    int j = i2 / KD, d = i2 - j*KD;
    KT[d*33 + j] = keyb[(size_t)(s0 + 2*j) * KD + d];
  }
  __syncthreads();
  for (int rr = 0; rr < 8; rr++) {
    int r = w*8 + rr;
    float dot = 0.f;
    if (!(r & 1)) {
      int jj = r >> 1;
      for (int d = lane; d < KD; d += 32) dot += QT[d*65 + r] * KT[d*33 + jj];
#pragma unroll
      for (int o = 16; o; o >>= 1) dot += __shfl_xor_sync(0xffffffffu, dot, o);
    }
    if (lane == 0) {
      if (!(r & 1)) {
        float mold = mrow[r], mnew = fmaxf(mold, dot);
        float s = expf(mold - mnew);
        float pd = expf(dot - mnew);
        scl[r] = s;
        P[r*33 + 32] = pd;
        lrow[r] = lrow[r]*s + pd;
        mrow[r] = mnew;
      } else {
        scl[r] = 1.f;
        P[r*33 + 32] = 0.f;
      }
    }
  }
  __syncthreads();

  /* final rescale + diag add + /l + writeout */
  float* xb = g_x + ((size_t)h * BSn + (size_t)b * Sn + s0) * 256;
#pragma unroll
  for (int i = 0; i < 4; i++) {
    int q = ty*4 + i;
    float s = scl[q];
    float pd = P[q*33 + 32];
    int jj = q >> 1;
    float invl = 1.f / lrow[q];
#pragma unroll
    for (int c = 0; c < 16; c++) {
      float v = acc[i][c]*s + pd * KT[(c*16 + tx)*33 + jj];
      xb[(size_t)q*256 + c*16 + tx] = v * invl;
    }
  }
}

extern "C" void kernel_launch(void* const* d_in, const int* in_sizes, int n_in,
                              void* d_out, int out_size) {
  const float* hidden = (const float*)d_in[0];
  const float* wq     = (const float*)d_in[1];
  const float* wkv_a  = (const float*)d_in[2];
  const float* kvg    = (const float*)d_in[3];
  const float* kvb    = (const float*)d_in[4];
  const float* wkvb   = (const float*)d_in[5];
  const float* wo     = (const float*)d_in[6];
  const float* fcw    = (const float*)d_in[7];
  const float* fcb    = (const float*)d_in[8];
  const float* fpw    = (const float*)d_in[9];
  const float* fpb    = (const float*)d_in[10];
  float* out = (float*)d_out;

  float *pq, *pkv, *pqpack, *pwkT, *px, *pv;
  cudaGetSymbolAddress((void**)&pq, g_q);
  cudaGetSymbolAddress((void**)&pkv, g_kv);
  cudaGetSymbolAddress((void**)&pqpack, g_qpack);
  cudaGetSymbolAddress((void**)&pwkT, g_wkT);
  cudaGetSymbolAddress((void**)&px, g_x);
  cudaGetSymbolAddress((void**)&pv, g_v);

  cudaFuncSetAttribute(attn_kernel, cudaFuncAttributeMaxDynamicSharedMemorySize,
                       ATT_SMEM_FLOATS * 4);

  /* q = hidden @ wq^T  (4096 x 1536, K=2048) — tensor (mma.sync) */
  tgemm<<<dim3(12, 32), 256>>>(hidden, 2048, wq, 2048, pq, 1536, 4096, 1536, 2048, 1.f);
  /* kv = hidden @ wkv_a^T  (4096 x 288, K=2048) — tensor */
  tgemm<<<dim3(3, 32), 256>>>(hidden, 2048, wkv_a, 2048, pkv, KD, 4096, KD, 2048, 1.f);
  gateproj_kernel<<<Sn, 64>>>(fcw, fcb, fpw, fpb);
  ln_rope_kernel<<<BSn, 256>>>(kvg, kvb);
  gate_kernel<<<BSn, 128>>>();
  wkT_kernel<<<(Hn*KVRn*NOPEn)/256, 256>>>(wkvb);
  qpack_kernel<<<BSn, 256>>>();
  /* q_abs per head: (4096 x 256, K=64), scaled, into g_qpack cols 0..255 */
  sgemm_nt<<<dim3(2, 32, 16), 256>>>(pq, Hn*QKDn, QKDn,
                                     pwkT, NOPEn, (long long)KVRn*NOPEn,
                                     pqpack, KD, (long long)BSn*KD,
                                     4096, KVRn, NOPEn, SCALEF);
  attn_kernel<<<Bn*Hn*32, 256, ATT_SMEM_FLOATS * 4>>>();
  /* v-proj per head: (4096 x 64, K=256) into g_v columns h*64.. */
  sgemm_nt<<<dim3(1, 32, 16), 256>>>(px, KVRn, (long long)BSn*KVRn,
                                     wkvb + 64*256, KVRn, (long long)128*256,
                                     pv, Hn*Vn, Vn,
                                     4096, Vn, KVRn, 1.f);
  /* final = v @ wo^T (4096 x 2048, K=1024) — tensor */
  tgemm<<<dim3(16, 32), 256>>>(pv, Hn*Vn, wo, Hn*Vn, out, En, 4096, En, Hn*Vn, 1.f);
}

// round 5
// speedup vs baseline: 2.0997x; 1.6906x over previous
#include <cuda_runtime.h>
#include <cuda_bf16.h>
#include <math.h>
#include <stdint.h>

#define Bn 2
#define Sn 2048
#define En 2048
#define Hn 16
#define NOPEn 64
#define ROPEn 32
#define Vn 64
#define KVRn 256
#define QKDn 96
#define BSn (Bn*Sn)
#define KD 288                       /* KVR + ROPE packed row */
#define SCALEF 0.10206207261596577f  /* 96^-0.5 */
#define NEGB (-1e30f)
#define LN1E4_D128 0.07195578415606394f  /* ln(10000)/128 */
#define LN1E4_D16  0.5756462732485115f   /* ln(10000)/16  */

/* ---------------- scratch (device globals; no allocation) ---------------- */
__device__ __align__(16) float g_q[(size_t)BSn * Hn * QKDn];      // (row, h*96+d)
__device__ __align__(16) float g_kv[(size_t)BSn * KD];            // ln(kv_c) ++ rope(k_pe)
__device__ __align__(16) float g_key[(size_t)BSn * KD];           // kv_t ++ k_pe_t
__device__ __align__(16) float g_qpack[(size_t)Hn * BSn * KD];    // (h,row,288)
__device__ __align__(16) float g_wkT[(size_t)Hn * KVRn * NOPEn];  // (h,c,d)
__device__ __align__(16) float g_C2[Sn * 64];
__device__ __align__(16) float g_P2[Sn * 64];
__device__ __align__(16) float g_x[(size_t)Hn * BSn * KVRn];      // attention out pre-Vproj
__device__ __align__(16) float g_v[(size_t)BSn * Hn * Vn];        // per-head projected

/* ==================== mma.sync helpers ==================== */
__device__ __forceinline__ void mma16816(float* c, const uint32_t* a, const uint32_t* b) {
  asm volatile(
    "mma.sync.aligned.m16n8k16.row.col.f32.bf16.bf16.f32 "
    "{%0,%1,%2,%3}, {%4,%5,%6,%7}, {%8,%9}, {%0,%1,%2,%3};"
    : "+f"(c[0]), "+f"(c[1]), "+f"(c[2]), "+f"(c[3])
    : "r"(a[0]), "r"(a[1]), "r"(a[2]), "r"(a[3]), "r"(b[0]), "r"(b[1]));
}
#define LDM_X2T(r0_, r1_, addr) \
  asm volatile("ldmatrix.sync.aligned.m8n8.x2.trans.shared.b16 {%0,%1}, [%2];" \
               : "=r"(r0_), "=r"(r1_) : "r"(addr))

__device__ __forceinline__ uint32_t smem_u32(const void* p) {
  uint32_t a;
  asm("{ .reg .u64 t; cvta.to.shared.u64 t, %1; cvt.u32.u64 %0, t; }" : "=r"(a) : "l"(p));
  return a;
}
__device__ __forceinline__ uint32_t pack_hi(float x, float y) {
  __nv_bfloat16 hx = __float2bfloat16_rn(x);
  __nv_bfloat16 hy = __float2bfloat16_rn(y);
  return ((uint32_t)__bfloat16_as_ushort(hy) << 16) | __bfloat16_as_ushort(hx);
}
__device__ __forceinline__ uint32_t pack_lo(float x, float y) {
  __nv_bfloat16 hx = __float2bfloat16_rn(x);
  __nv_bfloat16 hy = __float2bfloat16_rn(y);
  __nv_bfloat16 lx = __float2bfloat16_rn(x - __bfloat162float(hx));
  __nv_bfloat16 ly = __float2bfloat16_rn(y - __bfloat162float(hy));
  return ((uint32_t)__bfloat16_as_ushort(ly) << 16) | __bfloat16_as_ushort(lx);
}
__device__ __forceinline__ float2 unpk(uint32_t u) {
  return make_float2(__bfloat162float(__ushort_as_bfloat16((unsigned short)(u & 0xffff))),
                     __bfloat162float(__ushort_as_bfloat16((unsigned short)(u >> 16))));
}

/* =============== batched tensor-core fp32-split GEMM: C = alpha*A[M,K]*B[N,K]^T ===== */
#define PITCH 20

__global__ __launch_bounds__(256, 1) void tgemm(
    const float* __restrict__ A, int lda, long long sA,
    const float* __restrict__ B, int ldb, long long sB,
    float* __restrict__ C, int ldc, long long sC,
    int M, int N, int K, float alpha)
{
  A += (size_t)blockIdx.z * sA;
  B += (size_t)blockIdx.z * sB;
  C += (size_t)blockIdx.z * sC;
  __shared__ uint32_t smAh[128 * PITCH];
  __shared__ uint32_t smAl[128 * PITCH];
  __shared__ uint32_t smBh[128 * PITCH];
  __shared__ uint32_t smBl[128 * PITCH];

  const int tid = threadIdx.x;
  const int wid = tid >> 5, lane = tid & 31;
  const int g = lane >> 2, q = lane & 3;
  const int wm = (wid & 1) * 64;
  const int wn = (wid >> 1) * 32;
  const int bm = blockIdx.y * 128, bn = blockIdx.x * 128;

  const int lrow = tid >> 1, lc = (tid & 1) * 16;
  const bool aok = (bm + lrow < M);
  const bool bok = (bn + lrow < N);
  const float* Arow = A + (size_t)(bm + lrow) * lda + lc;
  const float* Brow = B + (size_t)(bn + lrow) * ldb + lc;

  float acc[4][4][4];
#pragma unroll
  for (int i = 0; i < 4; i++)
#pragma unroll
    for (int j = 0; j < 4; j++)
#pragma unroll
      for (int t = 0; t < 4; t++) acc[i][j][t] = 0.f;

  float4 aR[4], bR[4];
  const float4 z4 = make_float4(0.f, 0.f, 0.f, 0.f);
#pragma unroll
  for (int i = 0; i < 4; i++) {
    aR[i] = aok ? *(const float4*)(Arow + 4 * i) : z4;
    bR[i] = bok ? *(const float4*)(Brow + 4 * i) : z4;
  }

  const int nk = K >> 5;
  for (int k = 0; k < nk; k++) {
    {
      int wo = lrow * PITCH + (lc >> 1);
#pragma unroll
      for (int i = 0; i < 4; i++) {
        float4 a = aR[i], b = bR[i];
        *(uint2*)&smAh[wo + 2 * i] = make_uint2(pack_hi(a.x, a.y), pack_hi(a.z, a.w));
        *(uint2*)&smAl[wo + 2 * i] = make_uint2(pack_lo(a.x, a.y), pack_lo(a.z, a.w));
        *(uint2*)&smBh[wo + 2 * i] = make_uint2(pack_hi(b.x, b.y), pack_hi(b.z, b.w));
        *(uint2*)&smBl[wo + 2 * i] = make_uint2(pack_lo(b.x, b.y), pack_lo(b.z, b.w));
      }
    }
    __syncthreads();
    if (k + 1 < nk) {
      int off = (k + 1) << 5;
#pragma unroll
      for (int i = 0; i < 4; i++) {
        aR[i] = aok ? *(const float4*)(Arow + off + 4 * i) : z4;
        bR[i] = bok ? *(const float4*)(Brow + off + 4 * i) : z4;
      }
    }
#pragma unroll
    for (int ks = 0; ks < 2; ks++) {
      uint32_t bh[4][2], bl[4][2];
#pragma unroll
      for (int nt = 0; nt < 4; nt++) {
        int r = (wn + nt * 8 + g) * PITCH + ks * 8 + q;
        bh[nt][0] = smBh[r]; bh[nt][1] = smBh[r + 4];
        bl[nt][0] = smBl[r]; bl[nt][1] = smBl[r + 4];
      }
#pragma unroll
      for (int mt = 0; mt < 4; mt++) {
        int r = (wm + mt * 16 + g) * PITCH + ks * 8 + q;
        uint32_t ah[4], al[4];
        ah[0] = smAh[r];     ah[1] = smAh[r + 8 * PITCH];
        ah[2] = smAh[r + 4]; ah[3] = smAh[r + 8 * PITCH + 4];
        al[0] = smAl[r];     al[1] = smAl[r + 8 * PITCH];
        al[2] = smAl[r + 4]; al[3] = smAl[r + 8 * PITCH + 4];
#pragma unroll
        for (int nt = 0; nt < 4; nt++) {
          mma16816(acc[mt][nt], ah, bh[nt]);
          mma16816(acc[mt][nt], ah, bl[nt]);
          mma16816(acc[mt][nt], al, bh[nt]);
        }
      }
    }
    __syncthreads();
  }

#pragma unroll
  for (int mt = 0; mt < 4; mt++) {
    int row = bm + wm + mt * 16 + g;
#pragma unroll
    for (int nt = 0; nt < 4; nt++) {
      int col = bn + wn + nt * 8 + q * 2;
      if (col < N) {
        if (row < M)
          *(float2*)(C + (size_t)row * ldc + col) =
            make_float2(alpha * acc[mt][nt][0], alpha * acc[mt][nt][1]);
        if (row + 8 < M)
          *(float2*)(C + (size_t)(row + 8) * ldc + col) =
            make_float2(alpha * acc[mt][nt][2], alpha * acc[mt][nt][3]);
      }
    }
  }
}

/* ============ C2/P2 projections of the positional encodings ============ */
__global__ void gateproj_kernel(const float* __restrict__ cw, const float* __restrict__ cb,
                                const float* __restrict__ pw, const float* __restrict__ pb) {
  int s = blockIdx.x;
  int tid = threadIdx.x;   // 64 threads
  __shared__ float prow[256], crow[256];
  for (int k = tid; k < 256; k += 64) {
    int i = k >> 1;
    float dv = expf(-(float)i * LN1E4_D128);
    float aP = (float)s * dv;
    float aC = (float)(s >> 1) * dv;
    prow[k] = (k & 1) ? cosf(aP) : sinf(aP);
    crow[k] = (k & 1) ? cosf(aC) : sinf(aC);
  }
  __syncthreads();
  float ap = pb[tid], ac = cb[tid];
  const float* pr = pw + tid * 256;
  const float* cr = cw + tid * 256;
  for (int k = 0; k < 256; k++) { ap += prow[k] * pr[k]; ac += crow[k] * cr[k]; }
  g_P2[s*64 + tid] = ap;
  g_C2[s*64 + tid] = ac;
}

/* ============ layernorm(kv_c) + rope(k_pe) in place on g_kv ============ */
__global__ void ln_rope_kernel(const float* __restrict__ gam, const float* __restrict__ bet) {
  int row = blockIdx.x;
  float* kv = g_kv + (size_t)row * KD;
  int tid = threadIdx.x;   // 256
  float x = kv[tid];
  float s1 = x, s2 = x * x;
#pragma unroll
  for (int o = 16; o; o >>= 1) {
    s1 += __shfl_xor_sync(0xffffffffu, s1, o);
    s2 += __shfl_xor_sync(0xffffffffu, s2, o);
  }
  __shared__ float r1[8], r2[8], mv[2];
  int lane = tid & 31, wid = tid >> 5;
  if (lane == 0) { r1[wid] = s1; r2[wid] = s2; }
  __syncthreads();
  if (tid == 0) {
    float a = 0.f, c = 0.f;
#pragma unroll
    for (int i = 0; i < 8; i++) { a += r1[i]; c += r2[i]; }
    float mean = a * (1.f / 256.f);
    mv[0] = mean;
    mv[1] = rsqrtf(c * (1.f / 256.f) - mean * mean + 1e-5f);
  }
  __syncthreads();
  kv[tid] = (x - mv[0]) * mv[1] * gam[tid] + bet[tid];
  if (tid < 16) {
    int s = row & (Sn - 1);
    float freq = expf(-(float)tid * LN1E4_D16);
    float ang = (float)s * freq;
    float cs = cosf(ang), sn = sinf(ang);
    float x0 = kv[256 + 2*tid], x1 = kv[256 + 2*tid + 1];
    kv[256 + 2*tid]     = x0*cs - x1*sn;
    kv[256 + 2*tid + 1] = x0*sn + x1*cs;
  }
}

/* ============ sparse Wg gating: g_key = kv_t ++ k_pe_t ============ */
__global__ void gate_kernel() {
  int row = blockIdx.x;
  int s = row & (Sn - 1);
  int tid = threadIdx.x;   // 128
  __shared__ float d1[64], d2[64], w2[2];
  if (tid < 64) {
    float c2 = g_C2[s*64 + tid];
    d1[tid] = c2 * g_P2[s*64 + tid];
    d2[tid] = (s & 1) ? c2 * g_P2[(s-1)*64 + tid] : 0.f;
  }
  __syncthreads();
  if (tid == 0) {
    float a = 0.f, b = 0.f;
    for (int i = 0; i < 64; i++) { a += d1[i]; b += d2[i]; }
    w2[0] = 1.f / (1.f + expf(-a));
    w2[1] = 1.f / (1.f + expf(-b));
  }
  __syncthreads();
  float wtt = w2[0], wpre = w2[1];
  const float* kvr = g_kv + (size_t)row * KD;
  float* dst = g_key + (size_t)row * KD;
  if (s & 1) {
    const float* kvp = kvr - KD;
    for (int c = tid; c < KD; c += 128) dst[c] = wtt * kvr[c] + wpre * kvp[c];
  } else {
    for (int c = tid; c < KD; c += 128) dst[c] = wtt * kvr[c];
  }
}

/* ============ transpose wkv_b first-64 rows per head: g_wkT[h][c][d] ============ */
__global__ void wkT_kernel(const float* __restrict__ wkvb) {
  int idx = blockIdx.x * 256 + threadIdx.x;   // < 16*256*64
  int d = idx & 63;
  int c = (idx >> 6) & 255;
  int h = idx >> 14;
  g_wkT[((size_t)h * 256 + c) * 64 + d] = wkvb[((size_t)h * 128 + d) * 256 + c];
}

/* ============ rope + scale q_pe into g_qpack[...,256:288] ============ */
__global__ void qpack_kernel() {
  int row = blockIdx.x;
  int tid = threadIdx.x;     // 256 = 16 heads * 16 pairs
  int h = tid >> 4, i = tid & 15;
  int s = row & (Sn - 1);
  const float* p = g_q + (size_t)row * (Hn*QKDn) + h*QKDn + NOPEn + 2*i;
  float freq = expf(-(float)i * LN1E4_D16);
  float ang = (float)s * freq;
  float cs = cosf(ang), sn = sinf(ang);
  float x0 = p[0], x1 = p[1];
  float* q = g_qpack + ((size_t)h * BSn + row) * KD + 256 + 2*i;
  q[0] = (x0*cs - x1*sn) * SCALEF;
  q[1] = (x0*sn + x1*cs) * SCALEF;
}

/* ============ tensor-core flash attention over compacted odd keys + diagonal ============
   Smem (u32): Qh/Ql 64x148, Kh/Kl 32x148, Pf 64x33 f32, Ph/Pl 64x20, stats 4x64. */
#define PQ 148
#define PP 20
#define ATT_SMEM_BYTES ((2*64*PQ + 2*32*PQ + 64*33 + 2*64*PP + 256) * 4)

__global__ __launch_bounds__(256, 1) void attn_mma() {
  extern __shared__ uint32_t sm4[];
  uint32_t* Qh = sm4;
  uint32_t* Ql = Qh + 64*PQ;
  uint32_t* Kh = Ql + 64*PQ;
  uint32_t* Kl = Kh + 32*PQ;
  float*    Pf = (float*)(Kl + 32*PQ);
  uint32_t* Ph = (uint32_t*)(Pf + 64*33);
  uint32_t* Pl = Ph + 64*PP;
  float* mrow = (float*)(Pl + 64*PP);
  float* lrow = mrow + 64;
  float* sclv = lrow + 64;
  float* pdv  = sclv + 64;

  const int tid = threadIdx.x;
  const int lane = tid & 31, w = tid >> 5;
  const int g = lane >> 2, q = lane & 3;
  const int wm = (w & 3) * 16;
  const int wn2 = w >> 2;   // 0/1

  int idx = blockIdx.x;
  int qt = 31 - (idx & 31);
  int bh = idx >> 5;
  int h = bh & 15, b = bh >> 4;
  int s0 = qt * 64;

  /* load Q tile 64x288 fp32 -> bf16 hi/lo */
  const float* qb = g_qpack + ((size_t)h * BSn + (size_t)b * Sn + s0) * KD;
  {
    int r = tid >> 2, p0 = tid & 3;
    for (int w2 = p0; w2 < 144; w2 += 4) {
      float2 v = *(const float2*)(qb + (size_t)r * KD + 2 * w2);
      Qh[r*PQ + w2] = pack_hi(v.x, v.y);
      Ql[r*PQ + w2] = pack_lo(v.x, v.y);
    }
  }
  if (tid < 64) { mrow[tid] = NEGB; lrow[tid] = 0.f; }

  float pacc[16][4];
#pragma unroll
  for (int nt = 0; nt < 16; nt++)
#pragma unroll
    for (int t = 0; t < 4; t++) pacc[nt][t] = 0.f;
  __syncthreads();

  const float* keyb = g_key + (size_t)b * Sn * KD;
  const uint32_t smU = smem_u32(sm4);
  const int l16 = lane & 15;
  const uint32_t khB = smU + (uint32_t)(2*64*PQ + l16*PQ) * 4;
  const uint32_t klB = khB + (uint32_t)(32*PQ) * 4;

  for (int it = 0; it <= qt; it++) {
    bool lastt = (it == qt);
    /* load 32 odd keys (t = 2*(32*it+j)+1) -> hi/lo */
    {
      int j = tid >> 3, p0 = tid & 7;
      const float* kr = keyb + (size_t)(2*(32*it + j) + 1) * KD;
      for (int w2 = p0; w2 < 144; w2 += 8) {
        float2 v = *(const float2*)(kr + 2 * w2);
        Kh[j*PQ + w2] = pack_hi(v.x, v.y);
        Kl[j*PQ + w2] = pack_lo(v.x, v.y);
      }
    }
    __syncthreads();

    /* scores 64x32: warp tile 16 rows x 16 cols, K=288 (18 k16 steps), 3-mma hi/lo */
    float sacc[2][4];
#pragma unroll
    for (int nt = 0; nt < 2; nt++)
#pragma unroll
      for (int t = 0; t < 4; t++) sacc[nt][t] = 0.f;
#pragma unroll
    for (int ks = 0; ks < 18; ks++) {
      int ra = (wm + g) * PQ + ks * 8 + q;
      uint32_t ah[4], al[4];
      ah[0] = Qh[ra];     ah[1] = Qh[ra + 8*PQ];
      ah[2] = Qh[ra + 4]; ah[3] = Qh[ra + 8*PQ + 4];
      al[0] = Ql[ra];     al[1] = Ql[ra + 8*PQ];
      al[2] = Ql[ra + 4]; al[3] = Ql[ra + 8*PQ + 4];
#pragma unroll
      for (int nt = 0; nt < 2; nt++) {
        int rb = (wn2*16 + nt*8 + g) * PQ + ks * 8 + q;
        uint32_t bhf[2] = { Kh[rb], Kh[rb + 4] };
        uint32_t blf[2] = { Kl[rb], Kl[rb + 4] };
        mma16816(sacc[nt], ah, bhf);
        mma16816(sacc[nt], ah, blf);
        mma16816(sacc[nt], al, bhf);
      }
    }
#pragma unroll
    for (int nt = 0; nt < 2; nt++) {
      int c = wn2*16 + nt*8 + 2*q;
      Pf[(wm+g)*33 + c]     = sacc[nt][0];
      Pf[(wm+g)*33 + c + 1] = sacc[nt][1];
      Pf[(wm+g+8)*33 + c]     = sacc[nt][2];
      Pf[(wm+g+8)*33 + c + 1] = sacc[nt][3];
    }
    __syncthreads();

    /* online softmax: 4 threads per row */
    {
      int r = tid >> 2, part = tid & 3;
      int jb = part * 8;
      float pv[8];
      float mx = NEGB;
#pragma unroll
      for (int i = 0; i < 8; i++) {
        float sc = Pf[r*33 + jb + i];
        if (lastt && (2*(32*it + jb + i) + 1 > s0 + r)) sc = NEGB;
        pv[i] = sc;
        mx = fmaxf(mx, sc);
      }
      mx = fmaxf(mx, __shfl_xor_sync(0xffffffffu, mx, 1));
      mx = fmaxf(mx, __shfl_xor_sync(0xffffffffu, mx, 2));
      float mold = mrow[r];
      float mnew = fmaxf(mold, mx);
      float su = 0.f;
#pragma unroll
      for (int i = 0; i < 8; i++) {
        float p = __expf(pv[i] - mnew);
        pv[i] = p; su += p;
      }
      su += __shfl_xor_sync(0xffffffffu, su, 1);
      su += __shfl_xor_sync(0xffffffffu, su, 2);
      if (part == 0) {
        float s = __expf(mold - mnew);
        sclv[r] = s;
        lrow[r] = lrow[r] * s + su;
        mrow[r] = mnew;
      }
#pragma unroll
      for (int ii = 0; ii < 4; ii++) {
        Ph[r*PP + part*4 + ii] = pack_hi(pv[2*ii], pv[2*ii+1]);
        Pl[r*PP + part*4 + ii] = pack_lo(pv[2*ii], pv[2*ii+1]);
      }
    }
    __syncthreads();

    /* rescale acc + PV: warp tile 16 rows x 128 cols, K=32 (2 k16), 3-mma hi/lo.
       B frags from Kh/Kl [j][d] via ldmatrix.x2.trans. */
    {
      float sl = sclv[wm + g], sh2 = sclv[wm + g + 8];
#pragma unroll
      for (int nt = 0; nt < 16; nt++) {
        pacc[nt][0] *= sl;  pacc[nt][1] *= sl;
        pacc[nt][2] *= sh2; pacc[nt][3] *= sh2;
      }
      uint32_t aph[2][4], apl[2][4];
#pragma unroll
      for (int ks = 0; ks < 2; ks++) {
        int rp = (wm + g) * PP + ks * 8 + q;
        aph[ks][0] = Ph[rp];     aph[ks][1] = Ph[rp + 8*PP];
        aph[ks][2] = Ph[rp + 4]; aph[ks][3] = Ph[rp + 8*PP + 4];
        apl[ks][0] = Pl[rp];     apl[ks][1] = Pl[rp + 8*PP];
        apl[ks][2] = Pl[rp + 4]; apl[ks][3] = Pl[rp + 8*PP + 4];
      }
#pragma unroll
      for (int nt = 0; nt < 16; nt++) {
        uint32_t co = (uint32_t)(wn2*64 + nt*4) * 4;
        uint32_t bh0[2], bl0[2], bh1[2], bl1[2];
        LDM_X2T(bh0[0], bh0[1], khB + co);
        LDM_X2T(bh1[0], bh1[1], khB + co + 16*PQ*4);
        LDM_X2T(bl0[0], bl0[1], klB + co);
        LDM_X2T(bl1[0], bl1[1], klB + co + 16*PQ*4);
        mma16816(pacc[nt], aph[0], bh0);
        mma16816(pacc[nt], aph[0], bl0);
        mma16816(pacc[nt], apl[0], bh0);
        mma16816(pacc[nt], aph[1], bh1);
        mma16816(pacc[nt], aph[1], bl1);
        mma16816(pacc[nt], apl[1], bh1);
      }
    }
    __syncthreads();
  }

  /* diagonal keys t = s0 + 2j */
  {
    int j = tid >> 3, p0 = tid & 7;
    const float* kr = keyb + (size_t)(s0 + 2*j) * KD;
    for (int w2 = p0; w2 < 144; w2 += 8) {
      float2 v = *(const float2*)(kr + 2 * w2);
      Kh[j*PQ + w2] = pack_hi(v.x, v.y);
      Kl[j*PQ + w2] = pack_lo(v.x, v.y);
    }
  }
  __syncthreads();
  {
    int r = tid >> 2, part = tid & 3;
    float dot = 0.f;
    if (!(r & 1)) {
      int jj = r >> 1;
      for (int w2 = part*36; w2 < part*36 + 36; w2++) {
        float2 qh = unpk(Qh[r*PQ + w2]);
        float2 ql = unpk(Ql[r*PQ + w2]);
        float2 kh = unpk(Kh[jj*PQ + w2]);
        float2 kl = unpk(Kl[jj*PQ + w2]);
        dot += qh.x*kh.x + qh.x*kl.x + ql.x*kh.x;
        dot += qh.y*kh.y + qh.y*kl.y + ql.y*kh.y;
      }
    }
    dot += __shfl_xor_sync(0xffffffffu, dot, 1);
    dot += __shfl_xor_sync(0xffffffffu, dot, 2);
    if (part == 0) {
      if (!(r & 1)) {
        float mold = mrow[r];
        float mnew = fmaxf(mold, dot);
        float s = __expf(mold - mnew);
        float pd = __expf(dot - mnew);
        sclv[r] = s; pdv[r] = pd;
        lrow[r] = lrow[r] * s + pd;
      } else {
        sclv[r] = 1.f; pdv[r] = 0.f;
      }
    }
  }
  __syncthreads();

  /* epilogue: acc*scl + pd*kv_diag, /l, writeout */
  {
    float* xb = g_x + ((size_t)h * BSn + (size_t)b * Sn + s0) * 256;
    int r0 = wm + g, r1 = wm + g + 8;
    float s0v = sclv[r0], s1v = sclv[r1];
    float p0v = pdv[r0],  p1v = pdv[r1];
    float il0 = 1.f / lrow[r0], il1 = 1.f / lrow[r1];
    bool ev = !(r0 & 1);
    int j0 = r0 >> 1, j1 = r1 >> 1;
#pragma unroll
    for (int nt = 0; nt < 16; nt++) {
      int c = wn2*128 + nt*8 + 2*q;
      float kv00 = 0.f, kv01 = 0.f, kv10 = 0.f, kv11 = 0.f;
      if (ev) {
        float2 h0 = unpk(Kh[j0*PQ + (c >> 1)]);
        float2 l0 = unpk(Kl[j0*PQ + (c >> 1)]);
        kv00 = h0.x + l0.x; kv01 = h0.y + l0.y;
        float2 h1 = unpk(Kh[j1*PQ + (c >> 1)]);
        float2 l1 = unpk(Kl[j1*PQ + (c >> 1)]);
        kv10 = h1.x + l1.x; kv11 = h1.y + l1.y;
      }
      *(float2*)(xb + (size_t)r0*256 + c) =
        make_float2((pacc[nt][0]*s0v + p0v*kv00)*il0, (pacc[nt][1]*s0v + p0v*kv01)*il0);
      *(float2*)(xb + (size_t)r1*256 + c) =
        make_float2((pacc[nt][2]*s1v + p1v*kv10)*il1, (pacc[nt][3]*s1v + p1v*kv11)*il1);
    }
  }
}

extern "C" void kernel_launch(void* const* d_in, const int* in_sizes, int n_in,
                              void* d_out, int out_size) {
  const float* hidden = (const float*)d_in[0];
  const float* wq     = (const float*)d_in[1];
  const float* wkv_a  = (const float*)d_in[2];
  const float* kvg    = (const float*)d_in[3];
  const float* kvb    = (const float*)d_in[4];
  const float* wkvb   = (const float*)d_in[5];
  const float* wo     = (const float*)d_in[6];
  const float* fcw    = (const float*)d_in[7];
  const float* fcb    = (const float*)d_in[8];
  const float* fpw    = (const float*)d_in[9];
  const float* fpb    = (const float*)d_in[10];
  float* out = (float*)d_out;

  float *pq, *pkv, *pqpack, *pwkT, *px, *pv;
  cudaGetSymbolAddress((void**)&pq, g_q);
  cudaGetSymbolAddress((void**)&pkv, g_kv);
  cudaGetSymbolAddress((void**)&pqpack, g_qpack);
  cudaGetSymbolAddress((void**)&pwkT, g_wkT);
  cudaGetSymbolAddress((void**)&px, g_x);
  cudaGetSymbolAddress((void**)&pv, g_v);

  cudaFuncSetAttribute(attn_mma, cudaFuncAttributeMaxDynamicSharedMemorySize,
                       ATT_SMEM_BYTES);

  /* q = hidden @ wq^T  (4096 x 1536, K=2048) */
  tgemm<<<dim3(12, 32, 1), 256>>>(hidden, 2048, 0, wq, 2048, 0,
                                  pq, 1536, 0, 4096, 1536, 2048, 1.f);
  /* kv = hidden @ wkv_a^T  (4096 x 288, K=2048) */
  tgemm<<<dim3(3, 32, 1), 256>>>(hidden, 2048, 0, wkv_a, 2048, 0,
                                 pkv, KD, 0, 4096, KD, 2048, 1.f);
  gateproj_kernel<<<Sn, 64>>>(fcw, fcb, fpw, fpb);
  ln_rope_kernel<<<BSn, 256>>>(kvg, kvb);
  gate_kernel<<<BSn, 128>>>();
  wkT_kernel<<<(Hn*KVRn*NOPEn)/256, 256>>>(wkvb);
  qpack_kernel<<<BSn, 256>>>();
  /* q_abs per head: (4096 x 256, K=64), scaled, into g_qpack cols 0..255 */
  tgemm<<<dim3(2, 32, 16), 256>>>(pq, Hn*QKDn, QKDn,
                                  pwkT, NOPEn, (long long)KVRn*NOPEn,
                                  pqpack, KD, (long long)BSn*KD,
                                  4096, KVRn, NOPEn, SCALEF);
  attn_mma<<<Bn*Hn*32, 256, ATT_SMEM_BYTES>>>();
  /* v-proj per head: (4096 x 64, K=256) into g_v columns h*64.. */
  tgemm<<<dim3(1, 32, 16), 256>>>(px, KVRn, (long long)BSn*KVRn,
                                  wkvb + 64*256, KVRn, (long long)128*256,
                                  pv, Hn*Vn, (long long)Vn,
                                  4096, Vn, KVRn, 1.f);
  /* final = v @ wo^T (4096 x 2048, K=1024) */
  tgemm<<<dim3(16, 32, 1), 256>>>(pv, Hn*Vn, 0, wo, Hn*Vn, 0,
                                  out, En, 0, 4096, En, Hn*Vn, 1.f);
}

// round 6
// speedup vs baseline: 2.4879x; 1.1849x over previous
#include <cuda_runtime.h>
#include <cuda_bf16.h>
#include <math.h>
#include <stdint.h>

#define Bn 2
#define Sn 2048
#define En 2048
#define Hn 16
#define NOPEn 64
#define ROPEn 32
#define Vn 64
#define KVRn 256
#define QKDn 96
#define BSn (Bn*Sn)
#define KD 288
#define KD2 144                      /* pairs per packed row */
#define SCALEF 0.10206207261596577f  /* 96^-0.5 */
#define NEGB (-1e30f)
#define LN1E4_D128 0.07195578415606394f
#define LN1E4_D16  0.5756462732485115f

/* ---------------- scratch (device globals; no allocation) ----------------
   hl format: uint2 per 2 floats; .x = packed bf16 hi pair, .y = packed lo pair. */
__device__ __align__(16) uint2 g_hid_hl[(size_t)BSn * 1024];        // hidden  4096x2048
__device__ __align__(16) uint2 g_wq_hl[(size_t)1536 * 1024];
__device__ __align__(16) uint2 g_wkva_hl[(size_t)KD * 1024];
__device__ __align__(16) uint2 g_wo_hl[(size_t)En * 512];
__device__ __align__(16) uint2 g_wkvb_hl[(size_t)Hn * 128 * 128];   // [h*128+d][128 pairs]
__device__ __align__(16) uint2 g_q_hl[(size_t)BSn * 768];           // q-proj out 4096x1536
__device__ __align__(16) float g_kv[(size_t)BSn * KD];              // fp32 (LN in place)
__device__ __align__(16) uint2 g_keyhl[(size_t)BSn * KD2];          // gated keys
__device__ __align__(16) uint2 g_qp_hl[(size_t)Hn * BSn * KD2];     // packed q per head
__device__ __align__(16) uint2 g_wkT_hl[(size_t)Hn * KVRn * 32];    // [h][c][32 pairs of d]
__device__ __align__(16) uint2 g_x_hl[(size_t)Hn * BSn * 128];      // attn out
__device__ __align__(16) uint2 g_v_hl[(size_t)BSn * 512];           // v-proj out 4096x1024
__device__ __align__(16) float g_C2[Sn * 64];
__device__ __align__(16) float g_P2[Sn * 64];

/* ==================== helpers ==================== */
__device__ __forceinline__ void mma16816(float* c, const uint32_t* a, const uint32_t* b) {
  asm volatile(
    "mma.sync.aligned.m16n8k16.row.col.f32.bf16.bf16.f32 "
    "{%0,%1,%2,%3}, {%4,%5,%6,%7}, {%8,%9}, {%0,%1,%2,%3};"
    : "+f"(c[0]), "+f"(c[1]), "+f"(c[2]), "+f"(c[3])
    : "r"(a[0]), "r"(a[1]), "r"(a[2]), "r"(a[3]), "r"(b[0]), "r"(b[1]));
}
#define LDM_X2T(r0_, r1_, addr) \
  asm volatile("ldmatrix.sync.aligned.m8n8.x2.trans.shared.b16 {%0,%1}, [%2];" \
               : "=r"(r0_), "=r"(r1_) : "r"(addr))

__device__ __forceinline__ uint32_t smem_u32(const void* p) {
  uint32_t a;
  asm("{ .reg .u64 t; cvta.to.shared.u64 t, %1; cvt.u32.u64 %0, t; }" : "=r"(a) : "l"(p));
  return a;
}
__device__ __forceinline__ uint32_t pack_hi(float x, float y) {
  __nv_bfloat16 hx = __float2bfloat16_rn(x);
  __nv_bfloat16 hy = __float2bfloat16_rn(y);
  return ((uint32_t)__bfloat16_as_ushort(hy) << 16) | __bfloat16_as_ushort(hx);
}
__device__ __forceinline__ uint32_t pack_lo(float x, float y) {
  __nv_bfloat16 hx = __float2bfloat16_rn(x);
  __nv_bfloat16 hy = __float2bfloat16_rn(y);
  __nv_bfloat16 lx = __float2bfloat16_rn(x - __bfloat162float(hx));
  __nv_bfloat16 ly = __float2bfloat16_rn(y - __bfloat162float(hy));
  return ((uint32_t)__bfloat16_as_ushort(ly) << 16) | __bfloat16_as_ushort(lx);
}
__device__ __forceinline__ uint2 pack_hl(float x, float y) {
  return make_uint2(pack_hi(x, y), pack_lo(x, y));
}
__device__ __forceinline__ float2 unpk(uint32_t u) {
  return make_float2(__bfloat162float(__ushort_as_bfloat16((unsigned short)(u & 0xffff))),
                     __bfloat162float(__ushort_as_bfloat16((unsigned short)(u >> 16))));
}

/* ============ generic fp32 -> hl converter ============ */
__global__ void conv_hl(const float* __restrict__ in, uint2* __restrict__ out, int npairs) {
  int i = blockIdx.x * 256 + threadIdx.x;
  if (i < npairs) {
    float2 v = ((const float2*)in)[i];
    out[i] = pack_hl(v.x, v.y);
  }
}

/* =============== batched tensor GEMM on hl inputs: C = alpha*A[M,K]*B[N,K]^T =========
   A2/B2: hl pairs, lda2/ldb2 in pairs. Output: Chl (pairs, ldc=pairs) or C fp32 (ldc=elems). */
#define PITCH 20

__global__ __launch_bounds__(256, 1) void tgemmB(
    const uint2* __restrict__ A2, int lda2, long long sA,
    const uint2* __restrict__ B2, int ldb2, long long sB,
    float* __restrict__ C, uint2* __restrict__ Chl, int ldc, long long sC,
    int M, int N, int K, float alpha)
{
  A2 += (size_t)blockIdx.z * sA;
  B2 += (size_t)blockIdx.z * sB;
  if (C)   C   += (size_t)blockIdx.z * sC;
  if (Chl) Chl += (size_t)blockIdx.z * sC;
  __shared__ uint32_t smAh[128 * PITCH];
  __shared__ uint32_t smAl[128 * PITCH];
  __shared__ uint32_t smBh[128 * PITCH];
  __shared__ uint32_t smBl[128 * PITCH];

  const int tid = threadIdx.x;
  const int wid = tid >> 5, lane = tid & 31;
  const int g = lane >> 2, q = lane & 3;
  const int wm = (wid & 1) * 64;
  const int wn = (wid >> 1) * 32;
  const int bm = blockIdx.y * 128, bn = blockIdx.x * 128;

  const int lrow = tid >> 1, half = tid & 1;
  const bool aok = (bm + lrow < M);
  const bool bok = (bn + lrow < N);
  const uint2* Arow = A2 + (size_t)(bm + lrow) * lda2 + half * 8;
  const uint2* Brow = B2 + (size_t)(bn + lrow) * ldb2 + half * 8;

  float acc[4][4][4];
#pragma unroll
  for (int i = 0; i < 4; i++)
#pragma unroll
    for (int j = 0; j < 4; j++)
#pragma unroll
      for (int t = 0; t < 4; t++) acc[i][j][t] = 0.f;

  uint4 aR[4], bR[4];
  const uint4 z4 = make_uint4(0u, 0u, 0u, 0u);
#pragma unroll
  for (int i = 0; i < 4; i++) {
    aR[i] = aok ? *(const uint4*)(Arow + 2 * i) : z4;
    bR[i] = bok ? *(const uint4*)(Brow + 2 * i) : z4;
  }

  const int nk = K >> 5;
  for (int k = 0; k < nk; k++) {
    {
      int wo = lrow * PITCH + half * 8;
#pragma unroll
      for (int i = 0; i < 4; i++) {
        *(uint2*)&smAh[wo + 2 * i] = make_uint2(aR[i].x, aR[i].z);
        *(uint2*)&smAl[wo + 2 * i] = make_uint2(aR[i].y, aR[i].w);
        *(uint2*)&smBh[wo + 2 * i] = make_uint2(bR[i].x, bR[i].z);
        *(uint2*)&smBl[wo + 2 * i] = make_uint2(bR[i].y, bR[i].w);
      }
    }
    __syncthreads();
    if (k + 1 < nk) {
      int off = (k + 1) * 16;
#pragma unroll
      for (int i = 0; i < 4; i++) {
        aR[i] = aok ? *(const uint4*)(Arow + off + 2 * i) : z4;
        bR[i] = bok ? *(const uint4*)(Brow + off + 2 * i) : z4;
      }
    }
#pragma unroll
    for (int ks = 0; ks < 2; ks++) {
      uint32_t bh[4][2], bl[4][2];
#pragma unroll
      for (int nt = 0; nt < 4; nt++) {
        int r = (wn + nt * 8 + g) * PITCH + ks * 8 + q;
        bh[nt][0] = smBh[r]; bh[nt][1] = smBh[r + 4];
        bl[nt][0] = smBl[r]; bl[nt][1] = smBl[r + 4];
      }
#pragma unroll
      for (int mt = 0; mt < 4; mt++) {
        int r = (wm + mt * 16 + g) * PITCH + ks * 8 + q;
        uint32_t ah[4], al[4];
        ah[0] = smAh[r];     ah[1] = smAh[r + 8 * PITCH];
        ah[2] = smAh[r + 4]; ah[3] = smAh[r + 8 * PITCH + 4];
        al[0] = smAl[r];     al[1] = smAl[r + 8 * PITCH];
        al[2] = smAl[r + 4]; al[3] = smAl[r + 8 * PITCH + 4];
#pragma unroll
        for (int nt = 0; nt < 4; nt++) {
          mma16816(acc[mt][nt], ah, bh[nt]);
          mma16816(acc[mt][nt], ah, bl[nt]);
          mma16816(acc[mt][nt], al, bh[nt]);
        }
      }
    }
    __syncthreads();
  }

#pragma unroll
  for (int mt = 0; mt < 4; mt++) {
    int row = bm + wm + mt * 16 + g;
#pragma unroll
    for (int nt = 0; nt < 4; nt++) {
      int col = bn + wn + nt * 8 + q * 2;
      if (col >= N) continue;
      float a0 = alpha * acc[mt][nt][0], a1 = alpha * acc[mt][nt][1];
      float a2 = alpha * acc[mt][nt][2], a3 = alpha * acc[mt][nt][3];
      if (Chl) {
        if (row < M)     Chl[(size_t)row * ldc + (col >> 1)]       = pack_hl(a0, a1);
        if (row + 8 < M) Chl[(size_t)(row + 8) * ldc + (col >> 1)] = pack_hl(a2, a3);
      } else {
        if (row < M)     *(float2*)(C + (size_t)row * ldc + col)       = make_float2(a0, a1);
        if (row + 8 < M) *(float2*)(C + (size_t)(row + 8) * ldc + col) = make_float2(a2, a3);
      }
    }
  }
}

/* ============ C2/P2 projections of the positional encodings ============ */
__global__ void gateproj_kernel(const float* __restrict__ cw, const float* __restrict__ cb,
                                const float* __restrict__ pw, const float* __restrict__ pb) {
  int s = blockIdx.x;
  int tid = threadIdx.x;   // 64 threads
  __shared__ float prow[256], crow[256];
  for (int k = tid; k < 256; k += 64) {
    int i = k >> 1;
    float dv = expf(-(float)i * LN1E4_D128);
    float aP = (float)s * dv;
    float aC = (float)(s >> 1) * dv;
    prow[k] = (k & 1) ? cosf(aP) : sinf(aP);
    crow[k] = (k & 1) ? cosf(aC) : sinf(aC);
  }
  __syncthreads();
  float ap = pb[tid], ac = cb[tid];
  const float* pr = pw + tid * 256;
  const float* cr = cw + tid * 256;
  for (int k = 0; k < 256; k++) { ap += prow[k] * pr[k]; ac += crow[k] * cr[k]; }
  g_P2[s*64 + tid] = ap;
  g_C2[s*64 + tid] = ac;
}

/* ============ layernorm(kv_c) + rope(k_pe) in place on g_kv ============ */
__global__ void ln_rope_kernel(const float* __restrict__ gam, const float* __restrict__ bet) {
  int row = blockIdx.x;
  float* kv = g_kv + (size_t)row * KD;
  int tid = threadIdx.x;   // 256
  float x = kv[tid];
  float s1 = x, s2 = x * x;
#pragma unroll
  for (int o = 16; o; o >>= 1) {
    s1 += __shfl_xor_sync(0xffffffffu, s1, o);
    s2 += __shfl_xor_sync(0xffffffffu, s2, o);
  }
  __shared__ float r1[8], r2[8], mv[2];
  int lane = tid & 31, wid = tid >> 5;
  if (lane == 0) { r1[wid] = s1; r2[wid] = s2; }
  __syncthreads();
  if (tid == 0) {
    float a = 0.f, c = 0.f;
#pragma unroll
    for (int i = 0; i < 8; i++) { a += r1[i]; c += r2[i]; }
    float mean = a * (1.f / 256.f);
    mv[0] = mean;
    mv[1] = rsqrtf(c * (1.f / 256.f) - mean * mean + 1e-5f);
  }
  __syncthreads();
  kv[tid] = (x - mv[0]) * mv[1] * gam[tid] + bet[tid];
  if (tid < 16) {
    int s = row & (Sn - 1);
    float freq = expf(-(float)tid * LN1E4_D16);
    float ang = (float)s * freq;
    float cs = cosf(ang), sn = sinf(ang);
    float x0 = kv[256 + 2*tid], x1 = kv[256 + 2*tid + 1];
    kv[256 + 2*tid]     = x0*cs - x1*sn;
    kv[256 + 2*tid + 1] = x0*sn + x1*cs;
  }
}

/* ============ sparse Wg gating -> packed hl keys ============ */
__global__ void gate_kernel() {
  int row = blockIdx.x;
  int s = row & (Sn - 1);
  int tid = threadIdx.x;   // 128
  __shared__ float d1[64], d2[64], w2s[2];
  if (tid < 64) {
    float c2 = g_C2[s*64 + tid];
    d1[tid] = c2 * g_P2[s*64 + tid];
    d2[tid] = (s & 1) ? c2 * g_P2[(s-1)*64 + tid] : 0.f;
  }
  __syncthreads();
  if (tid == 0) {
    float a = 0.f, b = 0.f;
    for (int i = 0; i < 64; i++) { a += d1[i]; b += d2[i]; }
    w2s[0] = 1.f / (1.f + expf(-a));
    w2s[1] = 1.f / (1.f + expf(-b));
  }
  __syncthreads();
  float wtt = w2s[0], wpre = w2s[1];
  const float* kvr = g_kv + (size_t)row * KD;
  const float* kvp = kvr - KD;
  uint2* dst = g_keyhl + (size_t)row * KD2;
  bool odd = (s & 1);
  for (int c2 = tid; c2 < KD2; c2 += 128) {
    float v0 = wtt * kvr[2*c2],   v1 = wtt * kvr[2*c2+1];
    if (odd) { v0 += wpre * kvp[2*c2]; v1 += wpre * kvp[2*c2+1]; }
    dst[c2] = pack_hl(v0, v1);
  }
}

/* ============ wkv_b first-64 rows transposed per head -> hl [h][c][32 d-pairs] ======= */
__global__ void wkT_kernel(const float* __restrict__ wkvb) {
  int idx = blockIdx.x * 256 + threadIdx.x;   // < 16*256*32
  int d2 = idx & 31;
  int c = (idx >> 5) & 255;
  int h = idx >> 13;
  float v0 = wkvb[((size_t)h * 128 + 2*d2) * 256 + c];
  float v1 = wkvb[((size_t)h * 128 + 2*d2 + 1) * 256 + c];
  g_wkT_hl[((size_t)h * 256 + c) * 32 + d2] = pack_hl(v0, v1);
}

/* ============ rope + scale q_pe from g_q_hl into g_qp_hl pairs 128..143 ============ */
__global__ void qpack_kernel() {
  int row = blockIdx.x;
  int tid = threadIdx.x;     // 256 = 16 heads * 16 pairs
  int h = tid >> 4, i = tid & 15;
  int s = row & (Sn - 1);
  uint2 u = g_q_hl[(size_t)row * 768 + h*48 + 32 + i];
  float2 hi = unpk(u.x), lo = unpk(u.y);
  float x0 = hi.x + lo.x, x1 = hi.y + lo.y;
  float freq = expf(-(float)i * LN1E4_D16);
  float ang = (float)s * freq;
  float cs = cosf(ang), sn = sinf(ang);
  float y0 = (x0*cs - x1*sn) * SCALEF;
  float y1 = (x0*sn + x1*cs) * SCALEF;
  g_qp_hl[((size_t)h * BSn + row) * KD2 + 128 + i] = pack_hl(y0, y1);
}

/* ============ tensor-core flash attention (hl inputs) ============ */
#define PQ 148
#define PP 20
#define ATT_SMEM_BYTES ((2*64*PQ + 2*32*PQ + 64*33 + 2*64*PP + 256) * 4)

__global__ __launch_bounds__(256, 1) void attn_mma() {
  extern __shared__ uint32_t sm4[];
  uint32_t* Qh = sm4;
  uint32_t* Ql = Qh + 64*PQ;
  uint32_t* Kh = Ql + 64*PQ;
  uint32_t* Kl = Kh + 32*PQ;
  float*    Pf = (float*)(Kl + 32*PQ);
  uint32_t* Ph = (uint32_t*)(Pf + 64*33);
  uint32_t* Pl = Ph + 64*PP;
  float* mrow = (float*)(Pl + 64*PP);
  float* lrow = mrow + 64;
  float* sclv = lrow + 64;
  float* pdv  = sclv + 64;

  const int tid = threadIdx.x;
  const int lane = tid & 31, w = tid >> 5;
  const int g = lane >> 2, q = lane & 3;
  const int wm = (w & 3) * 16;
  const int wn2 = w >> 2;

  int idx = blockIdx.x;
  int qt = 31 - (idx & 31);
  int bh = idx >> 5;
  int h = bh & 15, b = bh >> 4;
  int s0 = qt * 64;

  /* load Q tile 64x288 (hl) */
  {
    int r = tid >> 2, p0 = tid & 3;
    const uint2* qr = g_qp_hl + ((size_t)h * BSn + (size_t)b * Sn + s0 + r) * KD2;
#pragma unroll 9
    for (int w2 = p0; w2 < 144; w2 += 4) {
      uint2 u = qr[w2];
      Qh[r*PQ + w2] = u.x;
      Ql[r*PQ + w2] = u.y;
    }
  }
  if (tid < 64) { mrow[tid] = NEGB; lrow[tid] = 0.f; }

  float pacc[16][4];
#pragma unroll
  for (int nt = 0; nt < 16; nt++)
#pragma unroll
    for (int t = 0; t < 4; t++) pacc[nt][t] = 0.f;
  __syncthreads();

  const uint2* keyb = g_keyhl + (size_t)b * Sn * KD2;
  const uint32_t smU = smem_u32(sm4);
  const int l16 = lane & 15;
  const uint32_t khB = smU + (uint32_t)(2*64*PQ + l16*PQ) * 4;
  const uint32_t klB = khB + (uint32_t)(32*PQ) * 4;

  for (int it = 0; it <= qt; it++) {
    bool lastt = (it == qt);
    /* load 32 odd keys (hl) */
    {
      int j = tid >> 3, p0 = tid & 7;
      const uint2* kr = keyb + (size_t)(2*(32*it + j) + 1) * KD2;
#pragma unroll 18
      for (int w2 = p0; w2 < 144; w2 += 8) {
        uint2 u = kr[w2];
        Kh[j*PQ + w2] = u.x;
        Kl[j*PQ + w2] = u.y;
      }
    }
    __syncthreads();

    /* scores 64x32 */
    float sacc[2][4];
#pragma unroll
    for (int nt = 0; nt < 2; nt++)
#pragma unroll
      for (int t = 0; t < 4; t++) sacc[nt][t] = 0.f;
#pragma unroll
    for (int ks = 0; ks < 18; ks++) {
      int ra = (wm + g) * PQ + ks * 8 + q;
      uint32_t ah[4], al[4];
      ah[0] = Qh[ra];     ah[1] = Qh[ra + 8*PQ];
      ah[2] = Qh[ra + 4]; ah[3] = Qh[ra + 8*PQ + 4];
      al[0] = Ql[ra];     al[1] = Ql[ra + 8*PQ];
      al[2] = Ql[ra + 4]; al[3] = Ql[ra + 8*PQ + 4];
#pragma unroll
      for (int nt = 0; nt < 2; nt++) {
        int rb = (wn2*16 + nt*8 + g) * PQ + ks * 8 + q;
        uint32_t bhf[2] = { Kh[rb], Kh[rb + 4] };
        uint32_t blf[2] = { Kl[rb], Kl[rb + 4] };
        mma16816(sacc[nt], ah, bhf);
        mma16816(sacc[nt], ah, blf);
        mma16816(sacc[nt], al, bhf);
      }
    }
#pragma unroll
    for (int nt = 0; nt < 2; nt++) {
      int c = wn2*16 + nt*8 + 2*q;
      Pf[(wm+g)*33 + c]       = sacc[nt][0];
      Pf[(wm+g)*33 + c + 1]   = sacc[nt][1];
      Pf[(wm+g+8)*33 + c]     = sacc[nt][2];
      Pf[(wm+g+8)*33 + c + 1] = sacc[nt][3];
    }
    __syncthreads();

    /* online softmax: 4 threads per row */
    {
      int r = tid >> 2, part = tid & 3;
      int jb = part * 8;
      float pv[8];
      float mx = NEGB;
#pragma unroll
      for (int i = 0; i < 8; i++) {
        float sc = Pf[r*33 + jb + i];
        if (lastt && (2*(32*it + jb + i) + 1 > s0 + r)) sc = NEGB;
        pv[i] = sc;
        mx = fmaxf(mx, sc);
      }
      mx = fmaxf(mx, __shfl_xor_sync(0xffffffffu, mx, 1));
      mx = fmaxf(mx, __shfl_xor_sync(0xffffffffu, mx, 2));
      float mold = mrow[r];
      float mnew = fmaxf(mold, mx);
      float su = 0.f;
#pragma unroll
      for (int i = 0; i < 8; i++) {
        float p = __expf(pv[i] - mnew);
        pv[i] = p; su += p;
      }
      su += __shfl_xor_sync(0xffffffffu, su, 1);
      su += __shfl_xor_sync(0xffffffffu, su, 2);
      if (part == 0) {
        float s = __expf(mold - mnew);
        sclv[r] = s;
        lrow[r] = lrow[r] * s + su;
        mrow[r] = mnew;
      }
#pragma unroll
      for (int ii = 0; ii < 4; ii++) {
        Ph[r*PP + part*4 + ii] = pack_hi(pv[2*ii], pv[2*ii+1]);
        Pl[r*PP + part*4 + ii] = pack_lo(pv[2*ii], pv[2*ii+1]);
      }
    }
    __syncthreads();

    /* rescale + PV */
    {
      float sl = sclv[wm + g], sh2 = sclv[wm + g + 8];
#pragma unroll
      for (int nt = 0; nt < 16; nt++) {
        pacc[nt][0] *= sl;  pacc[nt][1] *= sl;
        pacc[nt][2] *= sh2; pacc[nt][3] *= sh2;
      }
      uint32_t aph[2][4], apl[2][4];
#pragma unroll
      for (int ks = 0; ks < 2; ks++) {
        int rp = (wm + g) * PP + ks * 8 + q;
        aph[ks][0] = Ph[rp];     aph[ks][1] = Ph[rp + 8*PP];
        aph[ks][2] = Ph[rp + 4]; aph[ks][3] = Ph[rp + 8*PP + 4];
        apl[ks][0] = Pl[rp];     apl[ks][1] = Pl[rp + 8*PP];
        apl[ks][2] = Pl[rp + 4]; apl[ks][3] = Pl[rp + 8*PP + 4];
      }
#pragma unroll
      for (int nt = 0; nt < 16; nt++) {
        uint32_t co = (uint32_t)(wn2*64 + nt*4) * 4;
        uint32_t bh0[2], bl0[2], bh1[2], bl1[2];
        LDM_X2T(bh0[0], bh0[1], khB + co);
        LDM_X2T(bh1[0], bh1[1], khB + co + 16*PQ*4);
        LDM_X2T(bl0[0], bl0[1], klB + co);
        LDM_X2T(bl1[0], bl1[1], klB + co + 16*PQ*4);
        mma16816(pacc[nt], aph[0], bh0);
        mma16816(pacc[nt], aph[0], bl0);
        mma16816(pacc[nt], apl[0], bh0);
        mma16816(pacc[nt], aph[1], bh1);
        mma16816(pacc[nt], aph[1], bl1);
        mma16816(pacc[nt], apl[1], bh1);
      }
    }
    __syncthreads();
  }

  /* diagonal keys t = s0 + 2j */
  {
    int j = tid >> 3, p0 = tid & 7;
    const uint2* kr = keyb + (size_t)(s0 + 2*j) * KD2;
#pragma unroll 18
    for (int w2 = p0; w2 < 144; w2 += 8) {
      uint2 u = kr[w2];
      Kh[j*PQ + w2] = u.x;
      Kl[j*PQ + w2] = u.y;
    }
  }
  __syncthreads();
  {
    int r = tid >> 2, part = tid & 3;
    float dot = 0.f;
    if (!(r & 1)) {
      int jj = r >> 1;
      for (int w2 = part*36; w2 < part*36 + 36; w2++) {
        float2 qh = unpk(Qh[r*PQ + w2]);
        float2 ql = unpk(Ql[r*PQ + w2]);
        float2 kh = unpk(Kh[jj*PQ + w2]);
        float2 kl = unpk(Kl[jj*PQ + w2]);
        dot += qh.x*kh.x + qh.x*kl.x + ql.x*kh.x;
        dot += qh.y*kh.y + qh.y*kl.y + ql.y*kh.y;
      }
    }
    dot += __shfl_xor_sync(0xffffffffu, dot, 1);
    dot += __shfl_xor_sync(0xffffffffu, dot, 2);
    if (part == 0) {
      if (!(r & 1)) {
        float mold = mrow[r];
        float mnew = fmaxf(mold, dot);
        float s = __expf(mold - mnew);
        float pd = __expf(dot - mnew);
        sclv[r] = s; pdv[r] = pd;
        lrow[r] = lrow[r] * s + pd;
      } else {
        sclv[r] = 1.f; pdv[r] = 0.f;
      }
    }
  }
  __syncthreads();

  /* epilogue -> g_x_hl */
  {
    uint2* xb = g_x_hl + ((size_t)h * BSn + (size_t)b * Sn + s0) * 128;
    int r0 = wm + g, r1 = wm + g + 8;
    float s0v = sclv[r0], s1v = sclv[r1];
    float p0v = pdv[r0],  p1v = pdv[r1];
    float il0 = 1.f / lrow[r0], il1 = 1.f / lrow[r1];
    bool ev = !(r0 & 1);
    int j0 = r0 >> 1, j1 = r1 >> 1;
#pragma unroll
    for (int nt = 0; nt < 16; nt++) {
      int c = wn2*128 + nt*8 + 2*q;
      float kv00 = 0.f, kv01 = 0.f, kv10 = 0.f, kv11 = 0.f;
      if (ev) {
        float2 h0 = unpk(Kh[j0*PQ + (c >> 1)]);
        float2 l0 = unpk(Kl[j0*PQ + (c >> 1)]);
        kv00 = h0.x + l0.x; kv01 = h0.y + l0.y;
        float2 h1 = unpk(Kh[j1*PQ + (c >> 1)]);
        float2 l1 = unpk(Kl[j1*PQ + (c >> 1)]);
        kv10 = h1.x + l1.x; kv11 = h1.y + l1.y;
      }
      float f0 = (pacc[nt][0]*s0v + p0v*kv00)*il0;
      float f1 = (pacc[nt][1]*s0v + p0v*kv01)*il0;
      float f2 = (pacc[nt][2]*s1v + p1v*kv10)*il1;
      float f3 = (pacc[nt][3]*s1v + p1v*kv11)*il1;
      xb[(size_t)r0*128 + (c >> 1)] = pack_hl(f0, f1);
      xb[(size_t)r1*128 + (c >> 1)] = pack_hl(f2, f3);
    }
  }
}

extern "C" void kernel_launch(void* const* d_in, const int* in_sizes, int n_in,
                              void* d_out, int out_size) {
  const float* hidden = (const float*)d_in[0];
  const float* wq     = (const float*)d_in[1];
  const float* wkv_a  = (const float*)d_in[2];
  const float* kvg    = (const float*)d_in[3];
  const float* kvb    = (const float*)d_in[4];
  const float* wkvb   = (const float*)d_in[5];
  const float* wo     = (const float*)d_in[6];
  const float* fcw    = (const float*)d_in[7];
  const float* fcb    = (const float*)d_in[8];
  const float* fpw    = (const float*)d_in[9];
  const float* fpb    = (const float*)d_in[10];
  float* out = (float*)d_out;

  uint2 *pHid, *pWq, *pWkva, *pWo, *pWkvb, *pQhl, *pQp, *pWkT, *pX, *pV;
  float *pKv;
  cudaGetSymbolAddress((void**)&pHid,  g_hid_hl);
  cudaGetSymbolAddress((void**)&pWq,   g_wq_hl);
  cudaGetSymbolAddress((void**)&pWkva, g_wkva_hl);
  cudaGetSymbolAddress((void**)&pWo,   g_wo_hl);
  cudaGetSymbolAddress((void**)&pWkvb, g_wkvb_hl);
  cudaGetSymbolAddress((void**)&pQhl,  g_q_hl);
  cudaGetSymbolAddress((void**)&pKv,   g_kv);
  cudaGetSymbolAddress((void**)&pQp,   g_qp_hl);
  cudaGetSymbolAddress((void**)&pWkT,  g_wkT_hl);
  cudaGetSymbolAddress((void**)&pX,    g_x_hl);
  cudaGetSymbolAddress((void**)&pV,    g_v_hl);

  cudaFuncSetAttribute(attn_mma, cudaFuncAttributeMaxDynamicSharedMemorySize,
                       ATT_SMEM_BYTES);

  /* converters */
  conv_hl<<<(BSn*1024 + 255)/256, 256>>>(hidden, pHid, BSn*1024);
  conv_hl<<<(1536*1024 + 255)/256, 256>>>(wq, pWq, 1536*1024);
  conv_hl<<<(KD*1024 + 255)/256, 256>>>(wkv_a, pWkva, KD*1024);
  conv_hl<<<(En*512 + 255)/256, 256>>>(wo, pWo, En*512);
  conv_hl<<<(Hn*128*128 + 255)/256, 256>>>(wkvb, pWkvb, Hn*128*128);
  wkT_kernel<<<(Hn*KVRn*32)/256, 256>>>(wkvb);

  /* q = hidden @ wq^T -> hl */
  tgemmB<<<dim3(12, 32, 1), 256>>>(pHid, 1024, 0, pWq, 1024, 0,
                                   nullptr, pQhl, 768, 0, 4096, 1536, 2048, 1.f);
  /* kv = hidden @ wkv_a^T -> fp32 */
  tgemmB<<<dim3(3, 32, 1), 256>>>(pHid, 1024, 0, pWkva, 1024, 0,
                                  pKv, nullptr, KD, 0, 4096, KD, 2048, 1.f);
  gateproj_kernel<<<Sn, 64>>>(fcw, fcb, fpw, fpb);
  ln_rope_kernel<<<BSn, 256>>>(kvg, kvb);
  gate_kernel<<<BSn, 128>>>();
  qpack_kernel<<<BSn, 256>>>();
  /* q_abs per head -> hl into g_qp_hl pairs 0..127 */
  tgemmB<<<dim3(2, 32, 16), 256>>>(pQhl, 768, 48,
                                   pWkT, 32, (long long)KVRn*32,
                                   nullptr, pQp, KD2, (long long)BSn*KD2,
                                   4096, KVRn, NOPEn, SCALEF);
  attn_mma<<<Bn*Hn*32, 256, ATT_SMEM_BYTES>>>();
  /* v-proj per head -> hl into g_v_hl cols h*32.. */
  tgemmB<<<dim3(1, 32, 16), 256>>>(pX, 128, (long long)BSn*128,
                                   pWkvb + 64*128, 128, (long long)128*128,
                                   nullptr, pV, 512, 32,
                                   4096, Vn, KVRn, 1.f);
  /* final = v @ wo^T -> fp32 out */
  tgemmB<<<dim3(16, 32, 1), 256>>>(pV, 512, 0, pWo, 512, 0,
                                   out, nullptr, En, 0, 4096, En, Hn*Vn, 1.f);
}